// round 2
// baseline (speedup 1.0000x reference)
#include <cuda_runtime.h>
#include <math.h>

// Problem constants
#define B_INS   8192
#define N_INS   16384        // 2*B_INS
#define DDIM    128
#define BP      256          // patch batches
#define PP      256          // patches per view
#define NP      512          // 2*PP
#define TEMP_INV 10.0f       // 1/TEMP
#define FIXED_MAX 10.0f      // logits <= 1/TEMP since |cos|<=1, diag excluded

// GEMM tiling
#define BM 128
#define BN 64
#define BSTR (BN + 4)        // 68, padded Bs row stride (floats)
#define JS 8                 // j-splits for instance GEMM
#define JT_PER (N_INS / BN / JS)   // 32 j-tiles per split

#define SMEM_BYTES ((BM * DDIM + DDIM * BSTR) * 4)   // 65536 + 34816 = 100352

// ---- scratch (device globals; no allocation allowed) ----
__device__ float  g_embsT[DDIM * N_INS];       // [k][i], 8 MB
__device__ float  g_patchT[BP * DDIM * NP];    // [b][k][j], 64 MB
__device__ int    g_valid[BP * NP];
__device__ float  g_row_sum[N_INS];
__device__ double g_loss_ins;
__device__ double g_loss_patch;
__device__ int    g_nvalid;

// ------------------------------------------------------------------
__global__ void k_init() {
    int t = blockIdx.x * blockDim.x + threadIdx.x;
    if (t < N_INS) g_row_sum[t] = 0.0f;
    if (t == 0) { g_loss_ins = 0.0; g_loss_patch = 0.0; g_nvalid = 0; }
}

// Normalize instance vectors, write K-major transposed embs
__global__ void k_norm_ins(const float* __restrict__ v1, const float* __restrict__ v2) {
    int warp = (blockIdx.x * blockDim.x + threadIdx.x) >> 5;
    int lane = threadIdx.x & 31;
    if (warp >= N_INS) return;
    const float* src = (warp < B_INS) ? (v1 + (size_t)warp * DDIM)
                                      : (v2 + (size_t)(warp - B_INS) * DDIM);
    float4 v = ((const float4*)src)[lane];
    float ss = v.x*v.x + v.y*v.y + v.z*v.z + v.w*v.w;
    #pragma unroll
    for (int o = 16; o; o >>= 1) ss += __shfl_xor_sync(0xffffffffu, ss, o);
    float inv = 1.0f / fmaxf(sqrtf(ss), 1e-12f);
    int k = lane * 4;
    g_embsT[(size_t)(k + 0) * N_INS + warp] = v.x * inv;
    g_embsT[(size_t)(k + 1) * N_INS + warp] = v.y * inv;
    g_embsT[(size_t)(k + 2) * N_INS + warp] = v.z * inv;
    g_embsT[(size_t)(k + 3) * N_INS + warp] = v.w * inv;
}

// Normalize patch vectors (norm over D at fixed (b,p)), write [b][k][j] layout,
// record validity flags and count valid entries.
__global__ void k_norm_patch(const float* __restrict__ v1, const float* __restrict__ v2,
                             const int* __restrict__ c1, const int* __restrict__ c2) {
    int b = blockIdx.x;
    int p = threadIdx.x;             // 256 threads
    const float* s1 = v1 + (size_t)b * DDIM * PP + p;
    const float* s2 = v2 + (size_t)b * DDIM * PP + p;
    float ss1 = 0.f, ss2 = 0.f;
    #pragma unroll 4
    for (int d = 0; d < DDIM; d++) {
        float a = s1[(size_t)d * PP]; ss1 += a * a;
        float c = s2[(size_t)d * PP]; ss2 += c * c;
    }
    float i1 = 1.0f / fmaxf(sqrtf(ss1), 1e-12f);
    float i2 = 1.0f / fmaxf(sqrtf(ss2), 1e-12f);
    float* dst = g_patchT + (size_t)b * DDIM * NP;
    #pragma unroll 4
    for (int d = 0; d < DDIM; d++) {
        dst[(size_t)d * NP + p]      = s1[(size_t)d * PP] * i1;
        dst[(size_t)d * NP + PP + p] = s2[(size_t)d * PP] * i2;
    }
    int f1 = (c1[b * PP + p] != 0);
    int f2 = (c2[b * PP + p] != 0);
    g_valid[b * NP + p]      = f1;
    g_valid[b * NP + PP + p] = f2;
    int cnt = __popc(__ballot_sync(0xffffffffu, f1)) + __popc(__ballot_sync(0xffffffffu, f2));
    if ((threadIdx.x & 31) == 0) atomicAdd(&g_nvalid, cnt);
}

// Instance GEMM + fused exp-sum. grid = (N_INS/BM, JS). Accumulates
// sum_j!=i exp(logit - 10) into g_row_sum[i].
extern "C" __global__ void __launch_bounds__(256, 2) k_ins_gemm() {
    extern __shared__ float smem[];
    float* As = smem;                 // [DDIM][BM], stride BM
    float* Bs = smem + DDIM * BM;     // [DDIM][BSTR]
    int t  = threadIdx.x;
    int tx = t & 15, ty = t >> 4;
    int i0 = blockIdx.x * BM;

    // Load A tile once: As[k][i] <- embsT[k][i0+i]
    #pragma unroll
    for (int r = 0; r < 16; r++) {
        int flat = r * 256 + t;
        int k = flat >> 5, iq = flat & 31;
        *(float4*)(As + k * BM + iq * 4) =
            *(const float4*)(g_embsT + (size_t)k * N_INS + i0 + iq * 4);
    }

    float rsum[8];
    #pragma unroll
    for (int u = 0; u < 8; u++) rsum[u] = 0.f;

    for (int jt = 0; jt < JT_PER; jt++) {
        int j0 = (blockIdx.y * JT_PER + jt) * BN;
        __syncthreads();
        #pragma unroll
        for (int r = 0; r < 8; r++) {
            int flat = r * 256 + t;
            int k = flat >> 4, jq = flat & 15;
            *(float4*)(Bs + k * BSTR + jq * 4) =
                *(const float4*)(g_embsT + (size_t)k * N_INS + j0 + jq * 4);
        }
        __syncthreads();

        float acc[8][4];
        #pragma unroll
        for (int u = 0; u < 8; u++)
            #pragma unroll
            for (int v = 0; v < 4; v++) acc[u][v] = 0.f;

        #pragma unroll 4
        for (int k = 0; k < DDIM; k++) {
            float4 a0 = *(const float4*)(As + k * BM + ty * 8);
            float4 a1 = *(const float4*)(As + k * BM + ty * 8 + 4);
            float4 bb = *(const float4*)(Bs + k * BSTR + tx * 4);
            float av[8] = {a0.x, a0.y, a0.z, a0.w, a1.x, a1.y, a1.z, a1.w};
            float bv[4] = {bb.x, bb.y, bb.z, bb.w};
            #pragma unroll
            for (int u = 0; u < 8; u++)
                #pragma unroll
                for (int v = 0; v < 4; v++)
                    acc[u][v] = fmaf(av[u], bv[v], acc[u][v]);
        }

        #pragma unroll
        for (int u = 0; u < 8; u++) {
            int gi = i0 + ty * 8 + u;
            #pragma unroll
            for (int v = 0; v < 4; v++) {
                int gj = j0 + tx * 4 + v;
                float l = acc[u][v] * TEMP_INV;
                if (gi != gj) rsum[u] += __expf(l - FIXED_MAX);
            }
        }
    }

    // Reduce over the 16 tx lanes sharing each row
    #pragma unroll
    for (int u = 0; u < 8; u++) {
        float s = rsum[u];
        #pragma unroll
        for (int o = 8; o; o >>= 1) s += __shfl_xor_sync(0xffffffffu, s, o);
        if (tx == 0) atomicAdd(&g_row_sum[i0 + ty * 8 + u], s);
    }
}

// Per-row: positive logit + log-sum-exp -> instance loss
__global__ void k_ins_reduce() {
    int i = blockIdx.x * 256 + threadIdx.x;
    int ip = i ^ B_INS;
    float pos = 0.f;
    #pragma unroll 4
    for (int k = 0; k < DDIM; k++)
        pos = fmaf(g_embsT[(size_t)k * N_INS + i], g_embsT[(size_t)k * N_INS + ip], pos);
    float loss = logf(g_row_sum[i]) + FIXED_MAX - pos * TEMP_INV;
    __shared__ float red[256];
    red[threadIdx.x] = loss;
    __syncthreads();
    for (int o = 128; o; o >>= 1) {
        if (threadIdx.x < o) red[threadIdx.x] += red[threadIdx.x + o];
        __syncthreads();
    }
    if (threadIdx.x == 0) atomicAdd(&g_loss_ins, (double)red[0]);
}

// Patch GEMM + full fused CE per block (block covers all 512 columns).
// grid = (NP/BM = 4, BP = 256)
extern "C" __global__ void __launch_bounds__(256, 2) k_patch_gemm() {
    extern __shared__ float smem[];
    float* As = smem;
    float* Bs = smem + DDIM * BM;
    int t  = threadIdx.x;
    int tx = t & 15, ty = t >> 4;
    int i0 = blockIdx.x * BM;
    int b  = blockIdx.y;
    const float* base = g_patchT + (size_t)b * DDIM * NP;

    #pragma unroll
    for (int r = 0; r < 16; r++) {
        int flat = r * 256 + t;
        int k = flat >> 5, iq = flat & 31;
        *(float4*)(As + k * BM + iq * 4) =
            *(const float4*)(base + (size_t)k * NP + i0 + iq * 4);
    }

    float rsum[8], pos[8];
    #pragma unroll
    for (int u = 0; u < 8; u++) { rsum[u] = 0.f; pos[u] = 0.f; }

    for (int jt = 0; jt < NP / BN; jt++) {
        int j0 = jt * BN;
        __syncthreads();
        #pragma unroll
        for (int r = 0; r < 8; r++) {
            int flat = r * 256 + t;
            int k = flat >> 4, jq = flat & 15;
            *(float4*)(Bs + k * BSTR + jq * 4) =
                *(const float4*)(base + (size_t)k * NP + j0 + jq * 4);
        }
        __syncthreads();

        float acc[8][4];
        #pragma unroll
        for (int u = 0; u < 8; u++)
            #pragma unroll
            for (int v = 0; v < 4; v++) acc[u][v] = 0.f;

        #pragma unroll 4
        for (int k = 0; k < DDIM; k++) {
            float4 a0 = *(const float4*)(As + k * BM + ty * 8);
            float4 a1 = *(const float4*)(As + k * BM + ty * 8 + 4);
            float4 bb = *(const float4*)(Bs + k * BSTR + tx * 4);
            float av[8] = {a0.x, a0.y, a0.z, a0.w, a1.x, a1.y, a1.z, a1.w};
            float bv[4] = {bb.x, bb.y, bb.z, bb.w};
            #pragma unroll
            for (int u = 0; u < 8; u++)
                #pragma unroll
                for (int v = 0; v < 4; v++)
                    acc[u][v] = fmaf(av[u], bv[v], acc[u][v]);
        }

        #pragma unroll
        for (int u = 0; u < 8; u++) {
            int gi = i0 + ty * 8 + u;
            #pragma unroll
            for (int v = 0; v < 4; v++) {
                int gj = j0 + tx * 4 + v;
                float l = acc[u][v] * TEMP_INV;
                if (gi != gj) rsum[u] += __expf(l - FIXED_MAX);
                if (gj == (gi ^ PP)) pos[u] += l;   // exactly one hit per row
            }
        }
    }

    // Reduce rsum/pos across the 16 tx lanes of each row
    float part = 0.f;
    #pragma unroll
    for (int u = 0; u < 8; u++) {
        float s = rsum[u], q = pos[u];
        #pragma unroll
        for (int o = 8; o; o >>= 1) {
            s += __shfl_xor_sync(0xffffffffu, s, o);
            q += __shfl_xor_sync(0xffffffffu, q, o);
        }
        if (tx == 0) {
            int gi = i0 + ty * 8 + u;
            if (g_valid[b * NP + gi])
                part += logf(s) + FIXED_MAX - q;
        }
    }

    __syncthreads();           // done with As as GEMM tile
    As[t] = (tx == 0) ? part : 0.f;
    __syncthreads();
    if (t == 0) {
        float s = 0.f;
        for (int i = 0; i < 256; i++) s += As[i];
        atomicAdd(&g_loss_patch, (double)s);
    }
}

__global__ void k_final(float* out) {
    out[0] = (float)(g_loss_ins / (double)N_INS + g_loss_patch / (double)g_nvalid);
}

// ------------------------------------------------------------------
extern "C" void kernel_launch(void* const* d_in, const int* in_sizes, int n_in,
                              void* d_out, int out_size) {
    const float* v1i = (const float*)d_in[0];
    const float* v2i = (const float*)d_in[1];
    const float* v1p = (const float*)d_in[2];
    const float* v2p = (const float*)d_in[3];
    const int*   c1  = (const int*)d_in[4];
    const int*   c2  = (const int*)d_in[5];
    float* out = (float*)d_out;

    cudaFuncSetAttribute(k_ins_gemm,   cudaFuncAttributeMaxDynamicSharedMemorySize, SMEM_BYTES);
    cudaFuncSetAttribute(k_patch_gemm, cudaFuncAttributeMaxDynamicSharedMemorySize, SMEM_BYTES);

    k_init<<<N_INS / 256, 256>>>();
    k_norm_ins<<<N_INS / 8, 256>>>(v1i, v2i);
    k_norm_patch<<<BP, 256>>>(v1p, v2p, c1, c2);
    k_ins_gemm<<<dim3(N_INS / BM, JS), 256, SMEM_BYTES>>>();
    k_ins_reduce<<<N_INS / 256, 256>>>();
    k_patch_gemm<<<dim3(NP / BM, BP), 256, SMEM_BYTES>>>();
    k_final<<<1, 1>>>(out);
}

// round 5
// speedup vs baseline: 5.7571x; 5.7571x over previous
#include <cuda_runtime.h>
#include <cuda_bf16.h>
#include <math.h>
#include <stdint.h>

#define B_INS   8192
#define N_INS   16384
#define DDIM    128
#define BP      256
#define PP      256
#define NPX     512
#define TEMP_INV 10.0f
#define FMAXV   10.0f
#define SC      14.426950408889634f   // 10 * log2(e)
#define NT_INS  128                   // 16384 / 128 tiles
#define NPAIRS  (NT_INS * (NT_INS + 1) / 2)   // 8256

// ---- scratch (device globals; no allocation allowed) ----
__device__ __align__(16) __nv_bfloat16 g_embsB[(size_t)N_INS * DDIM];     // [i][k] 4MB
__device__ float  g_embsT[(size_t)DDIM * N_INS];                          // [k][i] 8MB (fp32 pos)
__device__ __align__(16) __nv_bfloat16 g_patchB[(size_t)BP * NPX * DDIM]; // [b][j][k] 32MB
__device__ int    g_valid[BP * NPX];
__device__ float  g_row_sum[N_INS];
__device__ double g_loss_ins;
__device__ double g_loss_patch;
__device__ int    g_nvalid;

// ------------------------- helpers -------------------------
__device__ __forceinline__ uint32_t smem_u32(const void* p) {
    uint32_t a;
    asm("{ .reg .u64 t; cvta.to.shared.u64 t, %1; cvt.u32.u64 %0, t; }" : "=r"(a) : "l"(p));
    return a;
}
__device__ __forceinline__ float ex2f(float x) {
    float r; asm("ex2.approx.ftz.f32 %0, %1;" : "=f"(r) : "f"(x)); return r;
}
__device__ __forceinline__ void ldsm4(uint32_t* r, uint32_t addr) {
    asm volatile("ldmatrix.sync.aligned.m8n8.x4.shared.b16 {%0,%1,%2,%3}, [%4];"
        : "=r"(r[0]), "=r"(r[1]), "=r"(r[2]), "=r"(r[3]) : "r"(addr));
}
__device__ __forceinline__ void mma16816(float* d, const uint32_t* a, const uint32_t* b) {
    asm volatile(
        "mma.sync.aligned.m16n8k16.row.col.f32.bf16.bf16.f32 "
        "{%0,%1,%2,%3}, {%4,%5,%6,%7}, {%8,%9}, {%0,%1,%2,%3};"
        : "+f"(d[0]), "+f"(d[1]), "+f"(d[2]), "+f"(d[3])
        : "r"(a[0]), "r"(a[1]), "r"(a[2]), "r"(a[3]), "r"(b[0]), "r"(b[1]));
}

// Load 128 rows x 128 bf16 (256B rows) global->smem with 16B-chunk XOR swizzle.
__device__ __forceinline__ void load_rows(char* dst, const __nv_bfloat16* __restrict__ src, int t) {
    #pragma unroll
    for (int it = 0; it < 8; it++) {
        int flat = it * 256 + t;
        int row = flat >> 4, c = flat & 15;
        *(uint4*)(dst + row * 256 + ((c ^ (row & 7)) << 4)) =
            *(const uint4*)(src + (size_t)row * DDIM + c * 8);
    }
}

// ------------------------- kernels -------------------------
__global__ void k_init() {
    int t = blockIdx.x * blockDim.x + threadIdx.x;
    if (t < N_INS) g_row_sum[t] = 0.0f;
    if (t == 0) { g_loss_ins = 0.0; g_loss_patch = 0.0; g_nvalid = 0; }
}

__global__ void k_norm_ins(const float* __restrict__ v1, const float* __restrict__ v2) {
    int warp = (blockIdx.x * blockDim.x + threadIdx.x) >> 5;
    int lane = threadIdx.x & 31;
    if (warp >= N_INS) return;
    const float* src = (warp < B_INS) ? (v1 + (size_t)warp * DDIM)
                                      : (v2 + (size_t)(warp - B_INS) * DDIM);
    float4 v = ((const float4*)src)[lane];
    float ss = v.x*v.x + v.y*v.y + v.z*v.z + v.w*v.w;
    #pragma unroll
    for (int o = 16; o; o >>= 1) ss += __shfl_xor_sync(0xffffffffu, ss, o);
    float inv = 1.0f / fmaxf(sqrtf(ss), 1e-12f);
    float x0 = v.x*inv, x1 = v.y*inv, x2 = v.z*inv, x3 = v.w*inv;
    int k = lane * 4;
    g_embsT[(size_t)(k + 0) * N_INS + warp] = x0;
    g_embsT[(size_t)(k + 1) * N_INS + warp] = x1;
    g_embsT[(size_t)(k + 2) * N_INS + warp] = x2;
    g_embsT[(size_t)(k + 3) * N_INS + warp] = x3;
    __nv_bfloat162* dst = (__nv_bfloat162*)(g_embsB + (size_t)warp * DDIM + k);
    dst[0] = __floats2bfloat162_rn(x0, x1);
    dst[1] = __floats2bfloat162_rn(x2, x3);
}

__global__ void k_norm_patch(const float* __restrict__ v1, const float* __restrict__ v2,
                             const int* __restrict__ c1, const int* __restrict__ c2) {
    extern __shared__ char psm[];
    float* s_inv = (float*)psm;      // 512 floats
    char*  buf   = psm + 2048;       // 256 rows x 272 bytes
    int b = blockIdx.x, p = threadIdx.x;
    const float* s1 = v1 + (size_t)b * DDIM * PP + p;
    const float* s2 = v2 + (size_t)b * DDIM * PP + p;
    float ss1 = 0.f, ss2 = 0.f;
    #pragma unroll 4
    for (int d = 0; d < DDIM; d++) {
        float a = s1[(size_t)d * PP]; ss1 += a * a;
        float c = s2[(size_t)d * PP]; ss2 += c * c;
    }
    s_inv[p]      = 1.0f / fmaxf(sqrtf(ss1), 1e-12f);
    s_inv[PP + p] = 1.0f / fmaxf(sqrtf(ss2), 1e-12f);

    int f1 = (c1[b * PP + p] != 0), f2 = (c2[b * PP + p] != 0);
    g_valid[b * NPX + p]      = f1;
    g_valid[b * NPX + PP + p] = f2;
    int cnt = __popc(__ballot_sync(0xffffffffu, f1)) + __popc(__ballot_sync(0xffffffffu, f2));
    if ((p & 31) == 0) atomicAdd(&g_nvalid, cnt);

    #pragma unroll
    for (int half = 0; half < 2; half++) {
        const float* src = half ? s2 : s1;
        float inv = half ? s_inv[PP + p] : s_inv[p];
        __syncthreads();
        #pragma unroll 4
        for (int d = 0; d < DDIM; d++) {
            float val = src[(size_t)d * PP] * inv;
            *(__nv_bfloat16*)(buf + p * 272 + d * 2) = __float2bfloat16(val);
        }
        __syncthreads();
        #pragma unroll
        for (int it = 0; it < 16; it++) {
            int flat = it * 256 + p;
            int row = flat >> 4, c = flat & 15;
            uint4 val = *(uint4*)(buf + row * 272 + c * 16);
            *(uint4*)(g_patchB + ((size_t)b * NPX + half * PP + row) * DDIM + c * 8) = val;
        }
    }
}

// Instance Gram tiles over upper triangle: HMMA 128x128x128 + fused exp-sum
// scattered to row sums (rows) and col sums (symmetric contribution).
// smem: A@0 32KB, B@32768 32KB, srows@65536 (128f), scols (+128f)
__global__ void __launch_bounds__(256, 2) k_ins_gemm() {
    extern __shared__ char smem[];
    float* srows = (float*)(smem + 65536);
    float* scols = srows + 128;
    int t = threadIdx.x, w = t >> 5, lane = t & 31;
    int g = lane >> 2, q = lane & 3;
    int wm = w >> 1, wn = w & 1;

    // linear block -> (bi <= bj) tile pair
    int bid = blockIdx.x;
    int bi = (int)((2.0 * NT_INS + 1.0
                    - sqrt((double)(2 * NT_INS + 1) * (2 * NT_INS + 1) - 8.0 * bid)) * 0.5);
    if (bi < 0) bi = 0;
    if (bi > NT_INS - 1) bi = NT_INS - 1;
    int base = bi * NT_INS - bi * (bi - 1) / 2;
    while (base + (NT_INS - bi) <= bid) { base += NT_INS - bi; bi++; }
    while (bid < base) { bi--; base -= NT_INS - bi; }
    int bj = bi + (bid - base);
    int i0 = bi * 128, j0 = bj * 128;
    bool diag = (bi == bj);

    load_rows(smem,         g_embsB + (size_t)i0 * DDIM, t);
    load_rows(smem + 32768, g_embsB + (size_t)j0 * DDIM, t);
    if (t < 128) { srows[t] = 0.f; scols[t] = 0.f; }
    __syncthreads();

    uint32_t sa = smem_u32(smem), sb = sa + 32768;
    float d[2][8][4];
    #pragma unroll
    for (int mt = 0; mt < 2; mt++)
        #pragma unroll
        for (int nt = 0; nt < 8; nt++)
            #pragma unroll
            for (int e = 0; e < 4; e++) d[mt][nt][e] = 0.f;

    int idx = lane >> 3, r = lane & 7;
    #pragma unroll
    for (int s = 0; s < 8; s++) {
        uint32_t aa[2][4], bb[4][4];
        #pragma unroll
        for (int mt = 0; mt < 2; mt++) {
            int row = wm * 32 + mt * 16 + (idx & 1) * 8 + r;
            int c = 2 * s + (idx >> 1);
            ldsm4(aa[mt], sa + row * 256 + ((c ^ (row & 7)) << 4));
        }
        #pragma unroll
        for (int p = 0; p < 4; p++) {
            int row = wn * 64 + p * 16 + (idx >> 1) * 8 + r;
            int c = 2 * s + (idx & 1);
            ldsm4(bb[p], sb + row * 256 + ((c ^ (row & 7)) << 4));
        }
        #pragma unroll
        for (int mt = 0; mt < 2; mt++)
            #pragma unroll
            for (int nt = 0; nt < 8; nt++)
                mma16816(d[mt][nt], aa[mt], &bb[nt >> 1][(nt & 1) * 2]);
    }

    // exp transform in place (mask diagonal elements on diagonal tiles)
    #pragma unroll
    for (int mt = 0; mt < 2; mt++)
        #pragma unroll
        for (int nt = 0; nt < 8; nt++)
            #pragma unroll
            for (int e = 0; e < 4; e++) {
                float v = ex2f(fmaf(d[mt][nt][e], SC, -SC));
                if (diag) {
                    int rl = wm * 32 + mt * 16 + g + ((e >> 1) << 3);
                    int cl = wn * 64 + nt * 8 + q * 2 + (e & 1);
                    if (rl == cl) v = 0.f;
                }
                d[mt][nt][e] = v;
            }

    // row partials -> quad reduce -> smem
    #pragma unroll
    for (int mt = 0; mt < 2; mt++) {
        float rp0 = 0.f, rp1 = 0.f;
        #pragma unroll
        for (int nt = 0; nt < 8; nt++) {
            rp0 += d[mt][nt][0] + d[mt][nt][1];
            rp1 += d[mt][nt][2] + d[mt][nt][3];
        }
        rp0 += __shfl_xor_sync(0xffffffffu, rp0, 1);
        rp0 += __shfl_xor_sync(0xffffffffu, rp0, 2);
        rp1 += __shfl_xor_sync(0xffffffffu, rp1, 1);
        rp1 += __shfl_xor_sync(0xffffffffu, rp1, 2);
        if (q == 0) {
            atomicAdd(&srows[wm * 32 + mt * 16 + g], rp0);
            atomicAdd(&srows[wm * 32 + mt * 16 + g + 8], rp1);
        }
    }
    // col partials -> reduce over row-groups -> smem
    #pragma unroll
    for (int nt = 0; nt < 8; nt++) {
        float c0 = d[0][nt][0] + d[0][nt][2] + d[1][nt][0] + d[1][nt][2];
        float c1 = d[0][nt][1] + d[0][nt][3] + d[1][nt][1] + d[1][nt][3];
        #pragma unroll
        for (int o = 4; o <= 16; o <<= 1) {
            c0 += __shfl_xor_sync(0xffffffffu, c0, o);
            c1 += __shfl_xor_sync(0xffffffffu, c1, o);
        }
        if (g == 0) {
            atomicAdd(&scols[wn * 64 + nt * 8 + q * 2], c0);
            atomicAdd(&scols[wn * 64 + nt * 8 + q * 2 + 1], c1);
        }
    }
    __syncthreads();
    if (t < 128) {
        atomicAdd(&g_row_sum[i0 + t], srows[t]);
        if (!diag) atomicAdd(&g_row_sum[j0 + t], scols[t]);
    }
}

__global__ void k_ins_reduce() {
    int i = blockIdx.x * 256 + threadIdx.x;
    int ip = i ^ B_INS;
    float pos = 0.f;
    #pragma unroll 4
    for (int k = 0; k < DDIM; k++)
        pos = fmaf(g_embsT[(size_t)k * N_INS + i], g_embsT[(size_t)k * N_INS + ip], pos);
    float loss = __logf(g_row_sum[i]) + FMAXV - pos * TEMP_INV;
    __shared__ float red[256];
    red[threadIdx.x] = loss;
    __syncthreads();
    for (int o = 128; o; o >>= 1) {
        if (threadIdx.x < o) red[threadIdx.x] += red[threadIdx.x + o];
        __syncthreads();
    }
    if (threadIdx.x == 0) atomicAdd(&g_loss_ins, (double)red[0]);
}

// Patch: 128 rows x full 512 cols per CTA, HMMA, fused per-row CE.
// grid = (4, BP). smem: A@0 32KB, B@32768 32KB, srows@65536, spos(+128), swrp(+256)
__global__ void __launch_bounds__(256, 2) k_patch_gemm() {
    extern __shared__ char smem[];
    float* srows = (float*)(smem + 65536);
    float* spos  = srows + 128;
    float* swrp  = spos + 128;
    int t = threadIdx.x, w = t >> 5, lane = t & 31;
    int g = lane >> 2, q = lane & 3;
    int wm = w >> 1, wn = w & 1;
    int i0 = blockIdx.x * 128, b = blockIdx.y;
    const __nv_bfloat16* bbase = g_patchB + (size_t)b * NPX * DDIM;

    load_rows(smem, bbase + (size_t)i0 * DDIM, t);
    if (t < 128) { srows[t] = 0.f; spos[t] = 0.f; }

    uint32_t sa = smem_u32(smem), sb = sa + 32768;
    int idx = lane >> 3, r = lane & 7;

    for (int jt = 0; jt < 4; jt++) {
        __syncthreads();
        load_rows(smem + 32768, bbase + (size_t)jt * 128 * DDIM, t);
        __syncthreads();

        float d[2][8][4];
        #pragma unroll
        for (int mt = 0; mt < 2; mt++)
            #pragma unroll
            for (int nt = 0; nt < 8; nt++)
                #pragma unroll
                for (int e = 0; e < 4; e++) d[mt][nt][e] = 0.f;

        #pragma unroll
        for (int s = 0; s < 8; s++) {
            uint32_t aa[2][4], bb[4][4];
            #pragma unroll
            for (int mt = 0; mt < 2; mt++) {
                int row = wm * 32 + mt * 16 + (idx & 1) * 8 + r;
                int c = 2 * s + (idx >> 1);
                ldsm4(aa[mt], sa + row * 256 + ((c ^ (row & 7)) << 4));
            }
            #pragma unroll
            for (int p = 0; p < 4; p++) {
                int row = wn * 64 + p * 16 + (idx >> 1) * 8 + r;
                int c = 2 * s + (idx & 1);
                ldsm4(bb[p], sb + row * 256 + ((c ^ (row & 7)) << 4));
            }
            #pragma unroll
            for (int mt = 0; mt < 2; mt++)
                #pragma unroll
                for (int nt = 0; nt < 8; nt++)
                    mma16816(d[mt][nt], aa[mt], &bb[nt >> 1][(nt & 1) * 2]);
        }

        bool dtile = (jt == blockIdx.x);
        #pragma unroll
        for (int mt = 0; mt < 2; mt++) {
            float rp0 = 0.f, rp1 = 0.f;
            #pragma unroll
            for (int nt = 0; nt < 8; nt++) {
                #pragma unroll
                for (int e = 0; e < 4; e++) {
                    int rl = wm * 32 + mt * 16 + g + ((e >> 1) << 3);
                    int cl = wn * 64 + nt * 8 + q * 2 + (e & 1);
                    int gi = i0 + rl, gj = jt * 128 + cl;
                    float l = d[mt][nt][e];
                    if (gj == (gi ^ PP)) spos[rl] = l;
                    float v = ex2f(fmaf(l, SC, -SC));
                    if (dtile && rl == cl) v = 0.f;
                    if (e >> 1) rp1 += v; else rp0 += v;
                }
            }
            rp0 += __shfl_xor_sync(0xffffffffu, rp0, 1);
            rp0 += __shfl_xor_sync(0xffffffffu, rp0, 2);
            rp1 += __shfl_xor_sync(0xffffffffu, rp1, 1);
            rp1 += __shfl_xor_sync(0xffffffffu, rp1, 2);
            if (q == 0) {
                atomicAdd(&srows[wm * 32 + mt * 16 + g], rp0);
                atomicAdd(&srows[wm * 32 + mt * 16 + g + 8], rp1);
            }
        }
    }
    __syncthreads();

    float part = 0.f;
    if (t < 128 && g_valid[b * NPX + i0 + t])
        part = __logf(srows[t]) + FMAXV - spos[t] * TEMP_INV;
    #pragma unroll
    for (int o = 16; o; o >>= 1) part += __shfl_xor_sync(0xffffffffu, part, o);
    if (lane == 0) swrp[w] = part;
    __syncthreads();
    if (t == 0) {
        float s = 0.f;
        #pragma unroll
        for (int i = 0; i < 8; i++) s += swrp[i];
        atomicAdd(&g_loss_patch, (double)s);
    }
}

__global__ void k_final(float* out) {
    out[0] = (float)(g_loss_ins / (double)N_INS + g_loss_patch / (double)g_nvalid);
}

// ------------------------------------------------------------------
#define SMEM_NORMP  (2048 + 256 * 272)      // 71680
#define SMEM_GEMM   (65536 + 2048)          // 67584

extern "C" void kernel_launch(void* const* d_in, const int* in_sizes, int n_in,
                              void* d_out, int out_size) {
    const float* v1i = (const float*)d_in[0];
    const float* v2i = (const float*)d_in[1];
    const float* v1p = (const float*)d_in[2];
    const float* v2p = (const float*)d_in[3];
    const int*   c1  = (const int*)d_in[4];
    const int*   c2  = (const int*)d_in[5];
    float* out = (float*)d_out;

    cudaFuncSetAttribute(k_norm_patch, cudaFuncAttributeMaxDynamicSharedMemorySize, SMEM_NORMP);
    cudaFuncSetAttribute(k_ins_gemm,   cudaFuncAttributeMaxDynamicSharedMemorySize, SMEM_GEMM);
    cudaFuncSetAttribute(k_patch_gemm, cudaFuncAttributeMaxDynamicSharedMemorySize, SMEM_GEMM);

    k_init<<<N_INS / 256, 256>>>();
    k_norm_ins<<<N_INS / 8, 256>>>(v1i, v2i);
    k_norm_patch<<<BP, 256, SMEM_NORMP>>>(v1p, v2p, c1, c2);
    k_ins_gemm<<<NPAIRS, 256, SMEM_GEMM>>>();
    k_ins_reduce<<<N_INS / 256, 256>>>();
    k_patch_gemm<<<dim3(4, BP), 256, SMEM_GEMM>>>();
    k_final<<<1, 1>>>(out);
}

// round 9
// speedup vs baseline: 5.8023x; 1.0079x over previous
#include <cuda_runtime.h>
#include <cuda_bf16.h>
#include <math.h>
#include <stdint.h>

#define B_INS   8192
#define N_INS   16384
#define DDIM    128
#define BP      256
#define PP      256
#define NPX     512
#define TEMP_INV 10.0f
#define FMAXV   10.0f
#define SC      14.426950408889634f   // 10 * log2(e)
#define NT_INS  128                   // 16384 / 128 tiles
#define NPAIRS  (NT_INS * (NT_INS + 1) / 2)   // 8256
#define NPTILE  4                     // 512/128 patch tiles per batch
#define NPPAIRS 10                    // upper-tri pairs of 4 tiles
#define PGRID   (BP * NPPAIRS)        // 2560

// ---- scratch (device globals; no allocation allowed) ----
__device__ __align__(16) __nv_bfloat16 g_embsB[(size_t)N_INS * DDIM];     // [i][k] 4MB
__device__ float  g_embsT[(size_t)DDIM * N_INS];                          // [k][i] 8MB (fp32 pos)
__device__ __align__(16) __nv_bfloat16 g_patchB[(size_t)BP * NPX * DDIM]; // [b][j][k] 32MB
__device__ int    g_valid[BP * NPX];
__device__ float  g_row_sum[N_INS];
__device__ float  g_prow[BP * NPX];
__device__ float  g_ppos[BP * NPX];
__device__ double g_loss_ins;
__device__ double g_loss_patch;
__device__ int    g_nvalid;

__constant__ int c_pti[NPPAIRS] = {0,0,0,0,1,1,1,2,2,3};
__constant__ int c_ptj[NPPAIRS] = {0,1,2,3,1,2,3,2,3,3};

// ------------------------- helpers -------------------------
__device__ __forceinline__ uint32_t smem_u32(const void* p) {
    uint32_t a;
    asm("{ .reg .u64 t; cvta.to.shared.u64 t, %1; cvt.u32.u64 %0, t; }" : "=r"(a) : "l"(p));
    return a;
}
__device__ __forceinline__ float ex2f(float x) {
    float r; asm("ex2.approx.ftz.f32 %0, %1;" : "=f"(r) : "f"(x)); return r;
}
__device__ __forceinline__ void ldsm4(uint32_t* r, uint32_t addr) {
    asm volatile("ldmatrix.sync.aligned.m8n8.x4.shared.b16 {%0,%1,%2,%3}, [%4];"
        : "=r"(r[0]), "=r"(r[1]), "=r"(r[2]), "=r"(r[3]) : "r"(addr));
}
__device__ __forceinline__ void mma16816(float* d, const uint32_t* a, const uint32_t* b) {
    asm volatile(
        "mma.sync.aligned.m16n8k16.row.col.f32.bf16.bf16.f32 "
        "{%0,%1,%2,%3}, {%4,%5,%6,%7}, {%8,%9}, {%0,%1,%2,%3};"
        : "+f"(d[0]), "+f"(d[1]), "+f"(d[2]), "+f"(d[3])
        : "r"(a[0]), "r"(a[1]), "r"(a[2]), "r"(a[3]), "r"(b[0]), "r"(b[1]));
}

// Load 128 rows x 128 bf16 (256B rows) global->smem with 16B-chunk XOR swizzle.
template<int NT>
__device__ __forceinline__ void load_rows(char* dst, const __nv_bfloat16* __restrict__ src, int t) {
    #pragma unroll
    for (int it = 0; it < 2048 / NT; it++) {
        int flat = it * NT + t;
        int row = flat >> 4, c = flat & 15;
        *(uint4*)(dst + row * 256 + ((c ^ (row & 7)) << 4)) =
            *(const uint4*)(src + (size_t)row * DDIM + c * 8);
    }
}

// Shared 128x128x128 HMMA mainloop body: 4 warps, 64x64 warp tiles.
// d[4][8][4] accumulators. sa/sb = smem addrs of A/B (swizzled 256B rows).
__device__ __forceinline__ void gemm128(float d[4][8][4], uint32_t sa, uint32_t sb,
                                        int wm, int wn, int lane) {
    int idx = lane >> 3, r = lane & 7;
    #pragma unroll
    for (int mt = 0; mt < 4; mt++)
        #pragma unroll
        for (int nt = 0; nt < 8; nt++)
            #pragma unroll
            for (int e = 0; e < 4; e++) d[mt][nt][e] = 0.f;
    #pragma unroll
    for (int s = 0; s < 8; s++) {
        uint32_t aa[4][4], bb[4][4];
        #pragma unroll
        for (int mt = 0; mt < 4; mt++) {
            int row = wm * 64 + mt * 16 + (idx & 1) * 8 + r;
            int c = 2 * s + (idx >> 1);
            ldsm4(aa[mt], sa + row * 256 + ((c ^ (row & 7)) << 4));
        }
        #pragma unroll
        for (int p = 0; p < 4; p++) {
            int row = wn * 64 + p * 16 + (idx >> 1) * 8 + r;
            int c = 2 * s + (idx & 1);
            ldsm4(bb[p], sb + row * 256 + ((c ^ (row & 7)) << 4));
        }
        #pragma unroll
        for (int mt = 0; mt < 4; mt++)
            #pragma unroll
            for (int nt = 0; nt < 8; nt++)
                mma16816(d[mt][nt], aa[mt], &bb[nt >> 1][(nt & 1) * 2]);
    }
}

// ------------------------- kernels -------------------------
__global__ void k_init() {
    int t = blockIdx.x * blockDim.x + threadIdx.x;
    if (t < N_INS) g_row_sum[t] = 0.0f;
    if (t < BP * NPX) g_prow[t] = 0.0f;
    if (t == 0) { g_loss_ins = 0.0; g_loss_patch = 0.0; g_nvalid = 0; }
}

__global__ void k_norm_ins(const float* __restrict__ v1, const float* __restrict__ v2) {
    int warp = (blockIdx.x * blockDim.x + threadIdx.x) >> 5;
    int lane = threadIdx.x & 31;
    if (warp >= N_INS) return;
    const float* src = (warp < B_INS) ? (v1 + (size_t)warp * DDIM)
                                      : (v2 + (size_t)(warp - B_INS) * DDIM);
    float4 v = ((const float4*)src)[lane];
    float ss = v.x*v.x + v.y*v.y + v.z*v.z + v.w*v.w;
    #pragma unroll
    for (int o = 16; o; o >>= 1) ss += __shfl_xor_sync(0xffffffffu, ss, o);
    float inv = 1.0f / fmaxf(sqrtf(ss), 1e-12f);
    float x0 = v.x*inv, x1 = v.y*inv, x2 = v.z*inv, x3 = v.w*inv;
    int k = lane * 4;
    g_embsT[(size_t)(k + 0) * N_INS + warp] = x0;
    g_embsT[(size_t)(k + 1) * N_INS + warp] = x1;
    g_embsT[(size_t)(k + 2) * N_INS + warp] = x2;
    g_embsT[(size_t)(k + 3) * N_INS + warp] = x3;
    __nv_bfloat162* dst = (__nv_bfloat162*)(g_embsB + (size_t)warp * DDIM + k);
    dst[0] = __floats2bfloat162_rn(x0, x1);
    dst[1] = __floats2bfloat162_rn(x2, x3);
}

__global__ void k_norm_patch(const float* __restrict__ v1, const float* __restrict__ v2,
                             const int* __restrict__ c1, const int* __restrict__ c2) {
    extern __shared__ char psm[];
    float* s_inv = (float*)psm;      // 512 floats
    char*  buf   = psm + 2048;       // 256 rows x 272 bytes
    int b = blockIdx.x, p = threadIdx.x;
    const float* s1 = v1 + (size_t)b * DDIM * PP + p;
    const float* s2 = v2 + (size_t)b * DDIM * PP + p;
    float ss1 = 0.f, ss2 = 0.f;
    #pragma unroll 4
    for (int d = 0; d < DDIM; d++) {
        float a = s1[(size_t)d * PP]; ss1 += a * a;
        float c = s2[(size_t)d * PP]; ss2 += c * c;
    }
    s_inv[p]      = 1.0f / fmaxf(sqrtf(ss1), 1e-12f);
    s_inv[PP + p] = 1.0f / fmaxf(sqrtf(ss2), 1e-12f);

    int f1 = (c1[b * PP + p] != 0), f2 = (c2[b * PP + p] != 0);
    g_valid[b * NPX + p]      = f1;
    g_valid[b * NPX + PP + p] = f2;
    int cnt = __popc(__ballot_sync(0xffffffffu, f1)) + __popc(__ballot_sync(0xffffffffu, f2));
    if ((p & 31) == 0) atomicAdd(&g_nvalid, cnt);

    #pragma unroll
    for (int half = 0; half < 2; half++) {
        const float* src = half ? s2 : s1;
        float inv = half ? s_inv[PP + p] : s_inv[p];
        __syncthreads();
        #pragma unroll 4
        for (int d = 0; d < DDIM; d++) {
            float val = src[(size_t)d * PP] * inv;
            *(__nv_bfloat16*)(buf + p * 272 + d * 2) = __float2bfloat16(val);
        }
        __syncthreads();
        #pragma unroll
        for (int it = 0; it < 16; it++) {
            int flat = it * 256 + p;
            int row = flat >> 4, c = flat & 15;
            uint4 val = *(uint4*)(buf + row * 272 + c * 16);
            *(uint4*)(g_patchB + ((size_t)b * NPX + half * PP + row) * DDIM + c * 8) = val;
        }
    }
}

// Instance Gram tiles over upper triangle: 128x128x128 HMMA, 64x64 warp tiles.
// smem: A@0 32KB, B@32768 32KB, srows@65536 (128f), scols (+128f)
__global__ void __launch_bounds__(128, 2) k_ins_gemm() {
    extern __shared__ char smem[];
    float* srows = (float*)(smem + 65536);
    float* scols = srows + 128;
    int t = threadIdx.x, w = t >> 5, lane = t & 31;
    int g = lane >> 2, q = lane & 3;
    int wm = w >> 1, wn = w & 1;

    // linear block -> (bi <= bj) tile pair
    int bid = blockIdx.x;
    int bi = (int)((2.0 * NT_INS + 1.0
                    - sqrt((double)(2 * NT_INS + 1) * (2 * NT_INS + 1) - 8.0 * bid)) * 0.5);
    if (bi < 0) bi = 0;
    if (bi > NT_INS - 1) bi = NT_INS - 1;
    int base = bi * NT_INS - bi * (bi - 1) / 2;
    while (base + (NT_INS - bi) <= bid) { base += NT_INS - bi; bi++; }
    while (bid < base) { bi--; base -= NT_INS - bi; }
    int bj = bi + (bid - base);
    int i0 = bi * 128, j0 = bj * 128;
    bool diag = (bi == bj);

    load_rows<128>(smem,         g_embsB + (size_t)i0 * DDIM, t);
    load_rows<128>(smem + 32768, g_embsB + (size_t)j0 * DDIM, t);
    srows[t] = 0.f; scols[t] = 0.f;
    __syncthreads();

    uint32_t sa = smem_u32(smem), sb = sa + 32768;
    float d[4][8][4];
    gemm128(d, sa, sb, wm, wn, lane);

    // exp transform in place (mask diagonal elements on diagonal tiles)
    #pragma unroll
    for (int mt = 0; mt < 4; mt++)
        #pragma unroll
        for (int nt = 0; nt < 8; nt++)
            #pragma unroll
            for (int e = 0; e < 4; e++) {
                float v = ex2f(fmaf(d[mt][nt][e], SC, -SC));
                if (diag) {
                    int rl = wm * 64 + mt * 16 + g + ((e >> 1) << 3);
                    int cl = wn * 64 + nt * 8 + q * 2 + (e & 1);
                    if (rl == cl) v = 0.f;
                }
                d[mt][nt][e] = v;
            }

    // row partials -> quad reduce -> smem
    #pragma unroll
    for (int mt = 0; mt < 4; mt++) {
        float rp0 = 0.f, rp1 = 0.f;
        #pragma unroll
        for (int nt = 0; nt < 8; nt++) {
            rp0 += d[mt][nt][0] + d[mt][nt][1];
            rp1 += d[mt][nt][2] + d[mt][nt][3];
        }
        rp0 += __shfl_xor_sync(0xffffffffu, rp0, 1);
        rp0 += __shfl_xor_sync(0xffffffffu, rp0, 2);
        rp1 += __shfl_xor_sync(0xffffffffu, rp1, 1);
        rp1 += __shfl_xor_sync(0xffffffffu, rp1, 2);
        if (q == 0) {
            atomicAdd(&srows[wm * 64 + mt * 16 + g], rp0);
            atomicAdd(&srows[wm * 64 + mt * 16 + g + 8], rp1);
        }
    }
    // col partials -> reduce over row-groups -> smem
    #pragma unroll
    for (int nt = 0; nt < 8; nt++) {
        float c0 = 0.f, c1 = 0.f;
        #pragma unroll
        for (int mt = 0; mt < 4; mt++) {
            c0 += d[mt][nt][0] + d[mt][nt][2];
            c1 += d[mt][nt][1] + d[mt][nt][3];
        }
        #pragma unroll
        for (int o = 4; o <= 16; o <<= 1) {
            c0 += __shfl_xor_sync(0xffffffffu, c0, o);
            c1 += __shfl_xor_sync(0xffffffffu, c1, o);
        }
        if (g == 0) {
            atomicAdd(&scols[wn * 64 + nt * 8 + q * 2], c0);
            atomicAdd(&scols[wn * 64 + nt * 8 + q * 2 + 1], c1);
        }
    }
    __syncthreads();
    atomicAdd(&g_row_sum[i0 + t], srows[t]);
    if (!diag) atomicAdd(&g_row_sum[j0 + t], scols[t]);
}

__global__ void k_ins_reduce() {
    int i = blockIdx.x * 256 + threadIdx.x;
    int ip = i ^ B_INS;
    float pos = 0.f;
    #pragma unroll 4
    for (int k = 0; k < DDIM; k++)
        pos = fmaf(g_embsT[(size_t)k * N_INS + i], g_embsT[(size_t)k * N_INS + ip], pos);
    float loss = __logf(g_row_sum[i]) + FMAXV - pos * TEMP_INV;
    __shared__ float red[256];
    red[threadIdx.x] = loss;
    __syncthreads();
    for (int o = 128; o; o >>= 1) {
        if (threadIdx.x < o) red[threadIdx.x] += red[threadIdx.x + o];
        __syncthreads();
    }
    if (threadIdx.x == 0) atomicAdd(&g_loss_ins, (double)red[0]);
}

// Patch Gram tiles over upper triangle per batch: grid = BP * 10.
// Row/col exp-sums scattered to g_prow, positives to g_ppos.
__global__ void __launch_bounds__(128, 2) k_patch_gemm() {
    extern __shared__ char smem[];
    float* srows = (float*)(smem + 65536);
    float* scols = srows + 128;
    int t = threadIdx.x, w = t >> 5, lane = t & 31;
    int g = lane >> 2, q = lane & 3;
    int wm = w >> 1, wn = w & 1;

    int b = blockIdx.x / NPPAIRS;
    int pi = blockIdx.x % NPPAIRS;
    int ti = c_pti[pi], tj = c_ptj[pi];
    int i0 = ti * 128, j0 = tj * 128;
    bool diag = (ti == tj);
    bool postile = (tj == (ti ^ 2));       // tiles containing j = i ^ 256
    int bofs = b * NPX;
    const __nv_bfloat16* bbase = g_patchB + (size_t)b * NPX * DDIM;

    load_rows<128>(smem,         bbase + (size_t)i0 * DDIM, t);
    load_rows<128>(smem + 32768, bbase + (size_t)j0 * DDIM, t);
    srows[t] = 0.f; scols[t] = 0.f;
    __syncthreads();

    uint32_t sa = smem_u32(smem), sb = sa + 32768;
    float d[4][8][4];
    gemm128(d, sa, sb, wm, wn, lane);

    #pragma unroll
    for (int mt = 0; mt < 4; mt++)
        #pragma unroll
        for (int nt = 0; nt < 8; nt++)
            #pragma unroll
            for (int e = 0; e < 4; e++) {
                int rl = wm * 64 + mt * 16 + g + ((e >> 1) << 3);
                int cl = wn * 64 + nt * 8 + q * 2 + (e & 1);
                float l = d[mt][nt][e];
                if (postile && (j0 + cl) == ((i0 + rl) ^ PP)) {
                    g_ppos[bofs + i0 + rl] = l;
                    g_ppos[bofs + j0 + cl] = l;
                }
                float v = ex2f(fmaf(l, SC, -SC));
                if (diag && rl == cl) v = 0.f;
                d[mt][nt][e] = v;
            }

    #pragma unroll
    for (int mt = 0; mt < 4; mt++) {
        float rp0 = 0.f, rp1 = 0.f;
        #pragma unroll
        for (int nt = 0; nt < 8; nt++) {
            rp0 += d[mt][nt][0] + d[mt][nt][1];
            rp1 += d[mt][nt][2] + d[mt][nt][3];
        }
        rp0 += __shfl_xor_sync(0xffffffffu, rp0, 1);
        rp0 += __shfl_xor_sync(0xffffffffu, rp0, 2);
        rp1 += __shfl_xor_sync(0xffffffffu, rp1, 1);
        rp1 += __shfl_xor_sync(0xffffffffu, rp1, 2);
        if (q == 0) {
            atomicAdd(&srows[wm * 64 + mt * 16 + g], rp0);
            atomicAdd(&srows[wm * 64 + mt * 16 + g + 8], rp1);
        }
    }
    #pragma unroll
    for (int nt = 0; nt < 8; nt++) {
        float c0 = 0.f, c1 = 0.f;
        #pragma unroll
        for (int mt = 0; mt < 4; mt++) {
            c0 += d[mt][nt][0] + d[mt][nt][2];
            c1 += d[mt][nt][1] + d[mt][nt][3];
        }
        #pragma unroll
        for (int o = 4; o <= 16; o <<= 1) {
            c0 += __shfl_xor_sync(0xffffffffu, c0, o);
            c1 += __shfl_xor_sync(0xffffffffu, c1, o);
        }
        if (g == 0) {
            atomicAdd(&scols[wn * 64 + nt * 8 + q * 2], c0);
            atomicAdd(&scols[wn * 64 + nt * 8 + q * 2 + 1], c1);
        }
    }
    __syncthreads();
    atomicAdd(&g_prow[bofs + i0 + t], srows[t]);
    if (!diag) atomicAdd(&g_prow[bofs + j0 + t], scols[t]);
}

// Per-(b,row) patch CE from accumulated sums.
__global__ void k_patch_reduce() {
    int i = blockIdx.x * 256 + threadIdx.x;
    float part = 0.f;
    if (g_valid[i])
        part = __logf(g_prow[i]) + FMAXV - g_ppos[i] * TEMP_INV;
    __shared__ float red[256];
    red[threadIdx.x] = part;
    __syncthreads();
    for (int o = 128; o; o >>= 1) {
        if (threadIdx.x < o) red[threadIdx.x] += red[threadIdx.x + o];
        __syncthreads();
    }
    if (threadIdx.x == 0) atomicAdd(&g_loss_patch, (double)red[0]);
}

__global__ void k_final(float* out) {
    out[0] = (float)(g_loss_ins / (double)N_INS + g_loss_patch / (double)g_nvalid);
}

// ------------------------------------------------------------------
#define SMEM_NORMP  (2048 + 256 * 272)      // 71680
#define SMEM_GEMM   (65536 + 1024)          // 66560

extern "C" void kernel_launch(void* const* d_in, const int* in_sizes, int n_in,
                              void* d_out, int out_size) {
    const float* v1i = (const float*)d_in[0];
    const float* v2i = (const float*)d_in[1];
    const float* v1p = (const float*)d_in[2];
    const float* v2p = (const float*)d_in[3];
    const int*   c1  = (const int*)d_in[4];
    const int*   c2  = (const int*)d_in[5];
    float* out = (float*)d_out;

    cudaFuncSetAttribute(k_norm_patch, cudaFuncAttributeMaxDynamicSharedMemorySize, SMEM_NORMP);
    cudaFuncSetAttribute(k_ins_gemm,   cudaFuncAttributeMaxDynamicSharedMemorySize, SMEM_GEMM);
    cudaFuncSetAttribute(k_patch_gemm, cudaFuncAttributeMaxDynamicSharedMemorySize, SMEM_GEMM);

    k_init<<<(BP * NPX) / 256, 256>>>();
    k_norm_ins<<<N_INS / 8, 256>>>(v1i, v2i);
    k_norm_patch<<<BP, 256, SMEM_NORMP>>>(v1p, v2p, c1, c2);
    k_ins_gemm<<<NPAIRS, 128, SMEM_GEMM>>>();
    k_ins_reduce<<<N_INS / 256, 256>>>();
    k_patch_gemm<<<PGRID, 128, SMEM_GEMM>>>();
    k_patch_reduce<<<(BP * NPX) / 256, 256>>>();
    k_final<<<1, 1>>>(out);
}

// round 10
// speedup vs baseline: 8.0719x; 1.3911x over previous
#include <cuda_runtime.h>
#include <cuda_bf16.h>
#include <math.h>
#include <stdint.h>

#define B_INS   8192
#define N_INS   16384
#define DDIM    128
#define BP      256
#define PP      256
#define NPX     512
#define TEMP_INV 10.0f
#define FMAXV   10.0f
#define SC      14.426950408889634f   // 10 * log2(e)
#define NT_INS  128
#define TOT_I   (NT_INS * (NT_INS + 1) / 2)   // 8256 tiles
#define CHUNK_I 28
#define GRID_I  295                            // ceil(8256/28)
#define TOT_P   (BP * 10)                      // 2560 tiles
#define CHUNK_P 9
#define GRID_P  285                            // ceil(2560/9)
#define SMEM_GEMM (3 * 32768)                  // A + B0 + B1

// ---- scratch (device globals; no allocation allowed) ----
__device__ __align__(16) __nv_bfloat16 g_embsB[(size_t)N_INS * DDIM];
__device__ float  g_embsT[(size_t)DDIM * N_INS];
__device__ __align__(16) __nv_bfloat16 g_patchB[(size_t)BP * NPX * DDIM];
__device__ int    g_valid[BP * NPX];
__device__ float  g_row_sum[N_INS];
__device__ float  g_prow[BP * NPX];
__device__ float  g_ppos[BP * NPX];
__device__ double g_loss_ins;
__device__ double g_loss_patch;
__device__ int    g_nvalid;

// ------------------------- helpers -------------------------
__device__ __forceinline__ uint32_t smem_u32(const void* p) {
    uint32_t a;
    asm("{ .reg .u64 t; cvta.to.shared.u64 t, %1; cvt.u32.u64 %0, t; }" : "=r"(a) : "l"(p));
    return a;
}
__device__ __forceinline__ float ex2f(float x) {
    float r; asm("ex2.approx.ftz.f32 %0, %1;" : "=f"(r) : "f"(x)); return r;
}
__device__ __forceinline__ void ldsm4(uint32_t* r, uint32_t addr) {
    asm volatile("ldmatrix.sync.aligned.m8n8.x4.shared.b16 {%0,%1,%2,%3}, [%4];"
        : "=r"(r[0]), "=r"(r[1]), "=r"(r[2]), "=r"(r[3]) : "r"(addr));
}
__device__ __forceinline__ void mma16816(float* d, const uint32_t* a, const uint32_t* b) {
    asm volatile(
        "mma.sync.aligned.m16n8k16.row.col.f32.bf16.bf16.f32 "
        "{%0,%1,%2,%3}, {%4,%5,%6,%7}, {%8,%9}, {%0,%1,%2,%3};"
        : "+f"(d[0]), "+f"(d[1]), "+f"(d[2]), "+f"(d[3])
        : "r"(a[0]), "r"(a[1]), "r"(a[2]), "r"(a[3]), "r"(b[0]), "r"(b[1]));
}
#define CP_COMMIT() asm volatile("cp.async.commit_group;")
#define CP_WAIT0()  asm volatile("cp.async.wait_group 0;")
#define CP_WAIT1()  asm volatile("cp.async.wait_group 1;")

// cp.async a 128x128 bf16 tile (256B rows) into swizzled smem. 128 threads.
__device__ __forceinline__ void cpa_rows(uint32_t dst, const __nv_bfloat16* __restrict__ src, int t) {
    #pragma unroll
    for (int it = 0; it < 16; it++) {
        int flat = it * 128 + t;
        int row = flat >> 4, c = flat & 15;
        uint32_t d = dst + row * 256 + ((c ^ (row & 7)) << 4);
        const void* g = src + (size_t)row * DDIM + c * 8;
        asm volatile("cp.async.cg.shared.global [%0], [%1], 16;" :: "r"(d), "l"(g));
    }
}
// sync global->smem loader (norm kernels don't need it; kept for reuse)
template<int NT>
__device__ __forceinline__ void load_rows(char* dst, const __nv_bfloat16* __restrict__ src, int t) {
    #pragma unroll
    for (int it = 0; it < 2048 / NT; it++) {
        int flat = it * NT + t;
        int row = flat >> 4, c = flat & 15;
        *(uint4*)(dst + row * 256 + ((c ^ (row & 7)) << 4)) =
            *(const uint4*)(src + (size_t)row * DDIM + c * 8);
    }
}

// 128x128x128 HMMA body: 4 warps, 64x64 warp tiles, d[4][8][4].
__device__ __forceinline__ void gemm128(float d[4][8][4], uint32_t sa, uint32_t sb,
                                        int wm, int wn, int lane) {
    int idx = lane >> 3, r = lane & 7;
    #pragma unroll
    for (int mt = 0; mt < 4; mt++)
        #pragma unroll
        for (int nt = 0; nt < 8; nt++)
            #pragma unroll
            for (int e = 0; e < 4; e++) d[mt][nt][e] = 0.f;
    #pragma unroll
    for (int s = 0; s < 8; s++) {
        uint32_t aa[4][4], bb[4][4];
        #pragma unroll
        for (int mt = 0; mt < 4; mt++) {
            int row = wm * 64 + mt * 16 + (idx & 1) * 8 + r;
            int c = 2 * s + (idx >> 1);
            ldsm4(aa[mt], sa + row * 256 + ((c ^ (row & 7)) << 4));
        }
        #pragma unroll
        for (int p = 0; p < 4; p++) {
            int row = wn * 64 + p * 16 + (idx >> 1) * 8 + r;
            int c = 2 * s + (idx & 1);
            ldsm4(bb[p], sb + row * 256 + ((c ^ (row & 7)) << 4));
        }
        #pragma unroll
        for (int mt = 0; mt < 4; mt++)
            #pragma unroll
            for (int nt = 0; nt < 8; nt++)
                mma16816(d[mt][nt], aa[mt], &bb[nt >> 1][(nt & 1) * 2]);
    }
}

// row-accumulator flush: shuffle-reduce across quads, atomic to dst[row]
__device__ __forceinline__ void flush_rows(float racc[4][2], float* dst, int wm, int lane) {
    int g = lane >> 2, q = lane & 3;
    #pragma unroll
    for (int mt = 0; mt < 4; mt++) {
        float r0 = racc[mt][0], r1 = racc[mt][1];
        r0 += __shfl_xor_sync(0xffffffffu, r0, 1);
        r0 += __shfl_xor_sync(0xffffffffu, r0, 2);
        r1 += __shfl_xor_sync(0xffffffffu, r1, 1);
        r1 += __shfl_xor_sync(0xffffffffu, r1, 2);
        if (q == 0) {
            atomicAdd(&dst[wm * 64 + mt * 16 + g], r0);
            atomicAdd(&dst[wm * 64 + mt * 16 + g + 8], r1);
        }
        racc[mt][0] = 0.f; racc[mt][1] = 0.f;
    }
}
// column scatter: shuffle-reduce across groups, atomic to dst[col]
__device__ __forceinline__ void scatter_cols(float d[4][8][4], float* dst, int wn, int lane) {
    int g = lane >> 2, q = lane & 3;
    #pragma unroll
    for (int n2 = 0; n2 < 8; n2++) {
        float c0 = 0.f, c1 = 0.f;
        #pragma unroll
        for (int mt = 0; mt < 4; mt++) {
            c0 += d[mt][n2][0] + d[mt][n2][2];
            c1 += d[mt][n2][1] + d[mt][n2][3];
        }
        #pragma unroll
        for (int o = 4; o <= 16; o <<= 1) {
            c0 += __shfl_xor_sync(0xffffffffu, c0, o);
            c1 += __shfl_xor_sync(0xffffffffu, c1, o);
        }
        if (g == 0) {
            atomicAdd(&dst[wn * 64 + n2 * 8 + q * 2], c0);
            atomicAdd(&dst[wn * 64 + n2 * 8 + q * 2 + 1], c1);
        }
    }
}

// tile-index decode: pair p = rows {p, 127-p}, 129 tiles
__device__ __forceinline__ void dec_ins(int u, int& bi, int& bj) {
    int p = u / 129, t = u - p * 129;
    int lenA = 128 - p;
    if (t < lenA) { bi = p; bj = p + t; }
    else { bi = 127 - p; bj = (127 - p) + (t - lenA); }
}
// patch: pair (b, ph): ph0 = rows {0,3} (5 tiles), ph1 = rows {1,2} (5 tiles)
__device__ __forceinline__ void dec_patch(int u, int& b, int& ti, int& tj) {
    int qq = u / 5, t = u - qq * 5;
    b = qq >> 1;
    if ((qq & 1) == 0) { if (t < 4) { ti = 0; tj = t; } else { ti = 3; tj = 3; } }
    else               { if (t < 3) { ti = 1; tj = 1 + t; } else { ti = 2; tj = t - 1; } }
}

// ------------------------- kernels -------------------------
__global__ void k_init() {
    int t = blockIdx.x * blockDim.x + threadIdx.x;
    if (t < N_INS) g_row_sum[t] = 0.0f;
    if (t < BP * NPX) g_prow[t] = 0.0f;
    if (t == 0) { g_loss_ins = 0.0; g_loss_patch = 0.0; g_nvalid = 0; }
}

__global__ void k_norm_ins(const float* __restrict__ v1, const float* __restrict__ v2) {
    int warp = (blockIdx.x * blockDim.x + threadIdx.x) >> 5;
    int lane = threadIdx.x & 31;
    if (warp >= N_INS) return;
    const float* src = (warp < B_INS) ? (v1 + (size_t)warp * DDIM)
                                      : (v2 + (size_t)(warp - B_INS) * DDIM);
    float4 v = ((const float4*)src)[lane];
    float ss = v.x*v.x + v.y*v.y + v.z*v.z + v.w*v.w;
    #pragma unroll
    for (int o = 16; o; o >>= 1) ss += __shfl_xor_sync(0xffffffffu, ss, o);
    float inv = 1.0f / fmaxf(sqrtf(ss), 1e-12f);
    float x0 = v.x*inv, x1 = v.y*inv, x2 = v.z*inv, x3 = v.w*inv;
    int k = lane * 4;
    g_embsT[(size_t)(k + 0) * N_INS + warp] = x0;
    g_embsT[(size_t)(k + 1) * N_INS + warp] = x1;
    g_embsT[(size_t)(k + 2) * N_INS + warp] = x2;
    g_embsT[(size_t)(k + 3) * N_INS + warp] = x3;
    __nv_bfloat162* dst = (__nv_bfloat162*)(g_embsB + (size_t)warp * DDIM + k);
    dst[0] = __floats2bfloat162_rn(x0, x1);
    dst[1] = __floats2bfloat162_rn(x2, x3);
}

__global__ void k_norm_patch(const float* __restrict__ v1, const float* __restrict__ v2,
                             const int* __restrict__ c1, const int* __restrict__ c2) {
    extern __shared__ char psm[];
    float* s_inv = (float*)psm;
    char*  buf   = psm + 2048;
    int b = blockIdx.x, p = threadIdx.x;
    const float* s1 = v1 + (size_t)b * DDIM * PP + p;
    const float* s2 = v2 + (size_t)b * DDIM * PP + p;
    float ss1 = 0.f, ss2 = 0.f;
    #pragma unroll 4
    for (int d = 0; d < DDIM; d++) {
        float a = s1[(size_t)d * PP]; ss1 += a * a;
        float c = s2[(size_t)d * PP]; ss2 += c * c;
    }
    s_inv[p]      = 1.0f / fmaxf(sqrtf(ss1), 1e-12f);
    s_inv[PP + p] = 1.0f / fmaxf(sqrtf(ss2), 1e-12f);

    int f1 = (c1[b * PP + p] != 0), f2 = (c2[b * PP + p] != 0);
    g_valid[b * NPX + p]      = f1;
    g_valid[b * NPX + PP + p] = f2;
    int cnt = __popc(__ballot_sync(0xffffffffu, f1)) + __popc(__ballot_sync(0xffffffffu, f2));
    if ((p & 31) == 0) atomicAdd(&g_nvalid, cnt);

    #pragma unroll
    for (int half = 0; half < 2; half++) {
        const float* src = half ? s2 : s1;
        float inv = half ? s_inv[PP + p] : s_inv[p];
        __syncthreads();
        #pragma unroll 4
        for (int d = 0; d < DDIM; d++) {
            float val = src[(size_t)d * PP] * inv;
            *(__nv_bfloat16*)(buf + p * 272 + d * 2) = __float2bfloat16(val);
        }
        __syncthreads();
        #pragma unroll
        for (int it = 0; it < 16; it++) {
            int flat = it * 256 + p;
            int row = flat >> 4, c = flat & 15;
            uint4 val = *(uint4*)(buf + row * 272 + c * 16);
            *(uint4*)(g_patchB + ((size_t)b * NPX + half * PP + row) * DDIM + c * 8) = val;
        }
    }
}

// Persistent instance GEMM: A-stationary, double-buffered B via cp.async.
__global__ void __launch_bounds__(128, 2) k_ins_gemm() {
    extern __shared__ char smem[];
    uint32_t sa = smem_u32(smem);
    uint32_t sb0 = sa + 32768, sb1 = sa + 65536;
    int t = threadIdx.x, w = t >> 5, lane = t & 31;
    int g = lane >> 2, q = lane & 3;
    int wm = w >> 1, wn = w & 1;
    int u0 = blockIdx.x * CHUNK_I;
    int u1 = min(u0 + CHUNK_I, TOT_I);
    int nt = u1 - u0;

    int bi, bj;
    dec_ins(u0, bi, bj);
    cpa_rows(sa,  g_embsB + (size_t)bi * 128 * DDIM, t);
    cpa_rows(sb0, g_embsB + (size_t)bj * 128 * DDIM, t);
    CP_COMMIT();
    if (nt > 1) {
        int bi1, bj1; dec_ins(u0 + 1, bi1, bj1);
        cpa_rows(sb1, g_embsB + (size_t)bj1 * 128 * DDIM, t);
    }
    CP_COMMIT();
    CP_WAIT1();
    __syncthreads();

    int curbi = bi;
    float racc[4][2] = {{0.f,0.f},{0.f,0.f},{0.f,0.f},{0.f,0.f}};

    for (int s = 0; s < nt; s++) {
        int tbi, tbj; dec_ins(u0 + s, tbi, tbj);
        uint32_t sbX = (s & 1) ? sb1 : sb0;
        float d[4][8][4];
        gemm128(d, sa, sbX, wm, wn, lane);

        bool diag = (tbi == tbj);
        #pragma unroll
        for (int mt = 0; mt < 4; mt++)
            #pragma unroll
            for (int n2 = 0; n2 < 8; n2++)
                #pragma unroll
                for (int e = 0; e < 4; e++) {
                    float v = ex2f(fmaf(d[mt][n2][e], SC, -SC));
                    if (diag) {
                        int rl = wm * 64 + mt * 16 + g + ((e >> 1) << 3);
                        int cl = wn * 64 + n2 * 8 + q * 2 + (e & 1);
                        if (rl == cl) v = 0.f;
                    }
                    d[mt][n2][e] = v;
                }
        #pragma unroll
        for (int mt = 0; mt < 4; mt++) {
            float rp0 = 0.f, rp1 = 0.f;
            #pragma unroll
            for (int n2 = 0; n2 < 8; n2++) {
                rp0 += d[mt][n2][0] + d[mt][n2][1];
                rp1 += d[mt][n2][2] + d[mt][n2][3];
            }
            racc[mt][0] += rp0; racc[mt][1] += rp1;
        }
        if (!diag) scatter_cols(d, &g_row_sum[tbj * 128], wn, lane);
        __syncthreads();                       // all reads of sbX (and sa) done

        if (s + 1 == nt) break;
        int nbi, nbj; dec_ins(u0 + s + 1, nbi, nbj);
        bool rel = (nbi != curbi);
        if (rel) {
            flush_rows(racc, &g_row_sum[curbi * 128], wm, lane);
            curbi = nbi;
            cpa_rows(sa, g_embsB + (size_t)nbi * 128 * DDIM, t);
        }
        if (s + 2 < nt) {
            int pbi, pbj; dec_ins(u0 + s + 2, pbi, pbj);
            cpa_rows(sbX, g_embsB + (size_t)pbj * 128 * DDIM, t);
        }
        CP_COMMIT();
        if (rel) { CP_WAIT0(); } else { CP_WAIT1(); }
        __syncthreads();
    }
    flush_rows(racc, &g_row_sum[curbi * 128], wm, lane);
}

__global__ void k_ins_reduce() {
    int i = blockIdx.x * 256 + threadIdx.x;
    int ip = i ^ B_INS;
    float pos = 0.f;
    #pragma unroll 4
    for (int k = 0; k < DDIM; k++)
        pos = fmaf(g_embsT[(size_t)k * N_INS + i], g_embsT[(size_t)k * N_INS + ip], pos);
    float loss = __logf(g_row_sum[i]) + FMAXV - pos * TEMP_INV;
    __shared__ float red[256];
    red[threadIdx.x] = loss;
    __syncthreads();
    for (int o = 128; o; o >>= 1) {
        if (threadIdx.x < o) red[threadIdx.x] += red[threadIdx.x + o];
        __syncthreads();
    }
    if (threadIdx.x == 0) atomicAdd(&g_loss_ins, (double)red[0]);
}

// Persistent patch GEMM: same pipeline, outputs g_prow/g_ppos.
__global__ void __launch_bounds__(128, 2) k_patch_gemm() {
    extern __shared__ char smem[];
    uint32_t sa = smem_u32(smem);
    uint32_t sb0 = sa + 32768, sb1 = sa + 65536;
    int t = threadIdx.x, w = t >> 5, lane = t & 31;
    int g = lane >> 2, q = lane & 3;
    int wm = w >> 1, wn = w & 1;
    int u0 = blockIdx.x * CHUNK_P;
    int u1 = min(u0 + CHUNK_P, TOT_P);
    int nt = u1 - u0;

    int b, ti, tj;
    dec_patch(u0, b, ti, tj);
    cpa_rows(sa,  g_patchB + ((size_t)b * NPX + ti * 128) * DDIM, t);
    cpa_rows(sb0, g_patchB + ((size_t)b * NPX + tj * 128) * DDIM, t);
    CP_COMMIT();
    if (nt > 1) {
        int b1, ti1, tj1; dec_patch(u0 + 1, b1, ti1, tj1);
        cpa_rows(sb1, g_patchB + ((size_t)b1 * NPX + tj1 * 128) * DDIM, t);
    }
    CP_COMMIT();
    CP_WAIT1();
    __syncthreads();

    int curb = b, curti = ti;
    float racc[4][2] = {{0.f,0.f},{0.f,0.f},{0.f,0.f},{0.f,0.f}};

    for (int s = 0; s < nt; s++) {
        int tb, tti, ttj; dec_patch(u0 + s, tb, tti, ttj);
        uint32_t sbX = (s & 1) ? sb1 : sb0;
        float d[4][8][4];
        gemm128(d, sa, sbX, wm, wn, lane);

        bool diag = (tti == ttj);
        bool postile = (ttj == (tti ^ 2));
        int bofs = tb * NPX, i0 = tti * 128, j0 = ttj * 128;
        #pragma unroll
        for (int mt = 0; mt < 4; mt++)
            #pragma unroll
            for (int n2 = 0; n2 < 8; n2++)
                #pragma unroll
                for (int e = 0; e < 4; e++) {
                    int rl = wm * 64 + mt * 16 + g + ((e >> 1) << 3);
                    int cl = wn * 64 + n2 * 8 + q * 2 + (e & 1);
                    float l = d[mt][n2][e];
                    if (postile && rl == cl) {       // j = i ^ 256 positives
                        g_ppos[bofs + i0 + rl] = l;
                        g_ppos[bofs + j0 + cl] = l;
                    }
                    float v = ex2f(fmaf(l, SC, -SC));
                    if (diag && rl == cl) v = 0.f;
                    d[mt][n2][e] = v;
                }
        #pragma unroll
        for (int mt = 0; mt < 4; mt++) {
            float rp0 = 0.f, rp1 = 0.f;
            #pragma unroll
            for (int n2 = 0; n2 < 8; n2++) {
                rp0 += d[mt][n2][0] + d[mt][n2][1];
                rp1 += d[mt][n2][2] + d[mt][n2][3];
            }
            racc[mt][0] += rp0; racc[mt][1] += rp1;
        }
        if (!diag) scatter_cols(d, &g_prow[bofs + j0], wn, lane);
        __syncthreads();

        if (s + 1 == nt) break;
        int nb, nti, ntj; dec_patch(u0 + s + 1, nb, nti, ntj);
        bool rel = (nb != curb) || (nti != curti);
        if (rel) {
            flush_rows(racc, &g_prow[curb * NPX + curti * 128], wm, lane);
            curb = nb; curti = nti;
            cpa_rows(sa, g_patchB + ((size_t)nb * NPX + nti * 128) * DDIM, t);
        }
        if (s + 2 < nt) {
            int pb, pti, ptj; dec_patch(u0 + s + 2, pb, pti, ptj);
            cpa_rows(sbX, g_patchB + ((size_t)pb * NPX + ptj * 128) * DDIM, t);
        }
        CP_COMMIT();
        if (rel) { CP_WAIT0(); } else { CP_WAIT1(); }
        __syncthreads();
    }
    flush_rows(racc, &g_prow[curb * NPX + curti * 128], wm, lane);
}

__global__ void k_patch_reduce() {
    int i = blockIdx.x * 256 + threadIdx.x;
    float part = 0.f;
    if (g_valid[i])
        part = __logf(g_prow[i]) + FMAXV - g_ppos[i] * TEMP_INV;
    __shared__ float red[256];
    red[threadIdx.x] = part;
    __syncthreads();
    for (int o = 128; o; o >>= 1) {
        if (threadIdx.x < o) red[threadIdx.x] += red[threadIdx.x + o];
        __syncthreads();
    }
    if (threadIdx.x == 0) atomicAdd(&g_loss_patch, (double)red[0]);
}

__global__ void k_final(float* out) {
    out[0] = (float)(g_loss_ins / (double)N_INS + g_loss_patch / (double)g_nvalid);
}

// ------------------------------------------------------------------
#define SMEM_NORMP  (2048 + 256 * 272)

extern "C" void kernel_launch(void* const* d_in, const int* in_sizes, int n_in,
                              void* d_out, int out_size) {
    const float* v1i = (const float*)d_in[0];
    const float* v2i = (const float*)d_in[1];
    const float* v1p = (const float*)d_in[2];
    const float* v2p = (const float*)d_in[3];
    const int*   c1  = (const int*)d_in[4];
    const int*   c2  = (const int*)d_in[5];
    float* out = (float*)d_out;

    cudaFuncSetAttribute(k_norm_patch, cudaFuncAttributeMaxDynamicSharedMemorySize, SMEM_NORMP);
    cudaFuncSetAttribute(k_ins_gemm,   cudaFuncAttributeMaxDynamicSharedMemorySize, SMEM_GEMM);
    cudaFuncSetAttribute(k_patch_gemm, cudaFuncAttributeMaxDynamicSharedMemorySize, SMEM_GEMM);

    k_init<<<(BP * NPX) / 256, 256>>>();
    k_norm_ins<<<N_INS / 8, 256>>>(v1i, v2i);
    k_norm_patch<<<BP, 256, SMEM_NORMP>>>(v1p, v2p, c1, c2);
    k_ins_gemm<<<GRID_I, 128, SMEM_GEMM>>>();
    k_ins_reduce<<<N_INS / 256, 256>>>();
    k_patch_gemm<<<GRID_P, 128, SMEM_GEMM>>>();
    k_patch_reduce<<<(BP * NPX) / 256, 256>>>();
    k_final<<<1, 1>>>(out);
}

// round 12
// speedup vs baseline: 8.4399x; 1.0456x over previous
#include <cuda_runtime.h>
#include <cuda_bf16.h>
#include <math.h>
#include <stdint.h>

#define B_INS   8192
#define N_INS   16384
#define DDIM    128
#define BP      256
#define PP      256
#define NPX     512
#define TEMP_INV 10.0f
#define SC      14.426950408889634f   // 10 * log2(e)
#define SHIFT   (-4.426950408889634f) // 10 - SC  (args biased +10 to stay f16-normal)
#define CADJ    3.0685281944f         // 10 - 10*ln2 (undo the +10 exponent bias)
#define NT_INS  128
#define TOT_I   (NT_INS * (NT_INS + 1) / 2)   // 8256
#define TOT_P   (BP * 10)                      // 2560
#define TOT_ALL (TOT_I + TOT_P)                // 10816
#define CHUNK   37
#define GRID_G  293                            // ceil(10816/37), one wave @2 CTA/SM
#define SMEM_GEMM (3 * 32768)

// ---- scratch (device globals; no allocation allowed) ----
__device__ __align__(16) __nv_bfloat16 g_embsB[(size_t)N_INS * DDIM];
__device__ float  g_embsT[(size_t)DDIM * N_INS];
__device__ __align__(16) __nv_bfloat16 g_patchB[(size_t)BP * NPX * DDIM];
__device__ int    g_valid[BP * NPX];
__device__ float  g_row_sum[N_INS];
__device__ float  g_prow[BP * NPX];
__device__ float  g_ppos[BP * NPX];
__device__ double g_loss_ins;
__device__ double g_loss_patch;
__device__ int    g_nvalid;

// ------------------------- helpers -------------------------
__device__ __forceinline__ uint32_t smem_u32(const void* p) {
    uint32_t a;
    asm("{ .reg .u64 t; cvta.to.shared.u64 t, %1; cvt.u32.u64 %0, t; }" : "=r"(a) : "l"(p));
    return a;
}
__device__ __forceinline__ void ldsm4(uint32_t* r, uint32_t addr) {
    asm volatile("ldmatrix.sync.aligned.m8n8.x4.shared.b16 {%0,%1,%2,%3}, [%4];"
        : "=r"(r[0]), "=r"(r[1]), "=r"(r[2]), "=r"(r[3]) : "r"(addr));
}
__device__ __forceinline__ void mma16816(float* d, const uint32_t* a, const uint32_t* b) {
    asm volatile(
        "mma.sync.aligned.m16n8k16.row.col.f32.bf16.bf16.f32 "
        "{%0,%1,%2,%3}, {%4,%5,%6,%7}, {%8,%9}, {%0,%1,%2,%3};"
        : "+f"(d[0]), "+f"(d[1]), "+f"(d[2]), "+f"(d[3])
        : "r"(a[0]), "r"(a[1]), "r"(a[2]), "r"(a[3]), "r"(b[0]), "r"(b[1]));
}
// pack two f32 args into f16x2 (lo=a0, hi=a1) and take 2^x of both
__device__ __forceinline__ uint32_t exp2pack(float a0, float a1) {
    uint32_t h;
    asm("{ .reg .b32 t; cvt.rn.f16x2.f32 t, %2, %1; ex2.approx.f16x2 %0, t; }"
        : "=r"(h) : "f"(a0), "f"(a1));
    return h;
}
__device__ __forceinline__ uint32_t hadd2v(uint32_t a, uint32_t b) {
    uint32_t r; asm("add.rn.f16x2 %0, %1, %2;" : "=r"(r) : "r"(a), "r"(b)); return r;
}
__device__ __forceinline__ float2 unpackh(uint32_t h) {
    float2 f;
    asm("{ .reg .b16 l, u; mov.b32 {l, u}, %2; cvt.f32.f16 %0, l; cvt.f32.f16 %1, u; }"
        : "=f"(f.x), "=f"(f.y) : "r"(h));
    return f;
}
#define CP_COMMIT() asm volatile("cp.async.commit_group;")
#define CP_WAIT0()  asm volatile("cp.async.wait_group 0;")
#define CP_WAIT1()  asm volatile("cp.async.wait_group 1;")

// cp.async a 128x128 bf16 tile (256B rows) into swizzled smem. 128 threads.
__device__ __forceinline__ void cpa_rows(uint32_t dst, const __nv_bfloat16* __restrict__ src, int t) {
    #pragma unroll
    for (int it = 0; it < 16; it++) {
        int flat = it * 128 + t;
        int row = flat >> 4, c = flat & 15;
        uint32_t d = dst + row * 256 + ((c ^ (row & 7)) << 4);
        const void* g = src + (size_t)row * DDIM + c * 8;
        asm volatile("cp.async.cg.shared.global [%0], [%1], 16;" :: "r"(d), "l"(g));
    }
}

// 128x128x128 HMMA body: 4 warps, 64x64 warp tiles, d[4][8][4].
__device__ __forceinline__ void gemm128(float d[4][8][4], uint32_t sa, uint32_t sb,
                                        int wm, int wn, int lane) {
    int idx = lane >> 3, r = lane & 7;
    #pragma unroll
    for (int mt = 0; mt < 4; mt++)
        #pragma unroll
        for (int nt = 0; nt < 8; nt++)
            #pragma unroll
            for (int e = 0; e < 4; e++) d[mt][nt][e] = 0.f;
    #pragma unroll
    for (int s = 0; s < 8; s++) {
        uint32_t aa[4][4], bb[4][4];
        #pragma unroll
        for (int mt = 0; mt < 4; mt++) {
            int row = wm * 64 + mt * 16 + (idx & 1) * 8 + r;
            int c = 2 * s + (idx >> 1);
            ldsm4(aa[mt], sa + row * 256 + ((c ^ (row & 7)) << 4));
        }
        #pragma unroll
        for (int p = 0; p < 4; p++) {
            int row = wn * 64 + p * 16 + (idx >> 1) * 8 + r;
            int c = 2 * s + (idx & 1);
            ldsm4(bb[p], sb + row * 256 + ((c ^ (row & 7)) << 4));
        }
        #pragma unroll
        for (int mt = 0; mt < 4; mt++)
            #pragma unroll
            for (int nt = 0; nt < 8; nt++)
                mma16816(d[mt][nt], aa[mt], &bb[nt >> 1][(nt & 1) * 2]);
    }
}

__device__ __forceinline__ void flush_rows(float racc[4][2], float* dst, int wm, int lane) {
    int g = lane >> 2, q = lane & 3;
    #pragma unroll
    for (int mt = 0; mt < 4; mt++) {
        float r0 = racc[mt][0], r1 = racc[mt][1];
        r0 += __shfl_xor_sync(0xffffffffu, r0, 1);
        r0 += __shfl_xor_sync(0xffffffffu, r0, 2);
        r1 += __shfl_xor_sync(0xffffffffu, r1, 1);
        r1 += __shfl_xor_sync(0xffffffffu, r1, 2);
        if (q == 0) {
            atomicAdd(&dst[wm * 64 + mt * 16 + g], r0);
            atomicAdd(&dst[wm * 64 + mt * 16 + g + 8], r1);
        }
        racc[mt][0] = 0.f; racc[mt][1] = 0.f;
    }
}

// tile decode
__device__ __forceinline__ void dec_ins(int u, int& bi, int& bj) {
    int p = u / 129, t = u - p * 129;
    int lenA = 128 - p;
    if (t < lenA) { bi = p; bj = p + t; }
    else { bi = 127 - p; bj = (127 - p) + (t - lenA); }
}
__device__ __forceinline__ void dec_patch(int u, int& b, int& ti, int& tj) {
    int qq = u / 5, t = u - qq * 5;
    b = qq >> 1;
    if ((qq & 1) == 0) { if (t < 4) { ti = 0; tj = t; } else { ti = 3; tj = 3; } }
    else               { if (t < 3) { ti = 1; tj = 1 + t; } else { ti = 2; tj = t - 1; } }
}

struct TileInfo {
    const __nv_bfloat16 *a, *b;
    float *rowdst, *coldst;
    float *posrow, *poscol;
    bool diag, postile;
};
__device__ __forceinline__ TileInfo dec_tile(int u) {
    TileInfo ti;
    if (u < TOT_I) {
        int bi, bj; dec_ins(u, bi, bj);
        ti.a = g_embsB + (size_t)bi * 128 * DDIM;
        ti.b = g_embsB + (size_t)bj * 128 * DDIM;
        ti.rowdst = &g_row_sum[bi * 128];
        ti.coldst = &g_row_sum[bj * 128];
        ti.diag = (bi == bj); ti.postile = false;
        ti.posrow = 0; ti.poscol = 0;
    } else {
        int b, t_i, t_j; dec_patch(u - TOT_I, b, t_i, t_j);
        ti.a = g_patchB + ((size_t)b * NPX + t_i * 128) * DDIM;
        ti.b = g_patchB + ((size_t)b * NPX + t_j * 128) * DDIM;
        ti.rowdst = &g_prow[b * NPX + t_i * 128];
        ti.coldst = &g_prow[b * NPX + t_j * 128];
        ti.diag = (t_i == t_j);
        ti.postile = (t_j == (t_i ^ 2));
        ti.posrow = &g_ppos[b * NPX + t_i * 128];
        ti.poscol = &g_ppos[b * NPX + t_j * 128];
    }
    return ti;
}

// ------------------------- kernels -------------------------
// instance norm + global zero-init (fused)
__global__ void k_norm_ins(const float* __restrict__ v1, const float* __restrict__ v2) {
    int gt = blockIdx.x * blockDim.x + threadIdx.x;
    if (gt < N_INS) g_row_sum[gt] = 0.0f;
    if (gt < BP * NPX) g_prow[gt] = 0.0f;
    if (gt == 0) { g_loss_ins = 0.0; g_loss_patch = 0.0; g_nvalid = 0; }

    int warp = gt >> 5;
    int lane = threadIdx.x & 31;
    if (warp >= N_INS) return;
    const float* src = (warp < B_INS) ? (v1 + (size_t)warp * DDIM)
                                      : (v2 + (size_t)(warp - B_INS) * DDIM);
    float4 v = ((const float4*)src)[lane];
    float ss = v.x*v.x + v.y*v.y + v.z*v.z + v.w*v.w;
    #pragma unroll
    for (int o = 16; o; o >>= 1) ss += __shfl_xor_sync(0xffffffffu, ss, o);
    float inv = 1.0f / fmaxf(sqrtf(ss), 1e-12f);
    float x0 = v.x*inv, x1 = v.y*inv, x2 = v.z*inv, x3 = v.w*inv;
    int k = lane * 4;
    g_embsT[(size_t)(k + 0) * N_INS + warp] = x0;
    g_embsT[(size_t)(k + 1) * N_INS + warp] = x1;
    g_embsT[(size_t)(k + 2) * N_INS + warp] = x2;
    g_embsT[(size_t)(k + 3) * N_INS + warp] = x3;
    __nv_bfloat162* dst = (__nv_bfloat162*)(g_embsB + (size_t)warp * DDIM + k);
    dst[0] = __floats2bfloat162_rn(x0, x1);
    dst[1] = __floats2bfloat162_rn(x2, x3);
}

// patch norm: single global pass via SMEM slab
#define SMEM_NORMP (131072 + 69632)   // slab[128][256] f32 + buf 256x272
__global__ void k_norm_patch(const float* __restrict__ v1, const float* __restrict__ v2,
                             const int* __restrict__ c1, const int* __restrict__ c2) {
    extern __shared__ char psm[];
    float* slab = (float*)psm;
    char*  buf  = psm + 131072;
    int b = blockIdx.x, p = threadIdx.x;

    int f1 = (c1[b * PP + p] != 0), f2 = (c2[b * PP + p] != 0);
    g_valid[b * NPX + p]      = f1;
    g_valid[b * NPX + PP + p] = f2;
    int cnt = __popc(__ballot_sync(0xffffffffu, f1)) + __popc(__ballot_sync(0xffffffffu, f2));
    if ((p & 31) == 0) atomicAdd(&g_nvalid, cnt);

    #pragma unroll
    for (int half = 0; half < 2; half++) {
        const float4* src = (const float4*)((half ? v2 : v1) + (size_t)b * DDIM * PP);
        float4* sl4 = (float4*)slab;
        #pragma unroll
        for (int it = 0; it < 32; it++)
            sl4[it * 256 + p] = src[it * 256 + p];
        __syncthreads();
        float ss = 0.f;
        #pragma unroll 4
        for (int d2 = 0; d2 < DDIM; d2++) { float a = slab[d2 * 256 + p]; ss += a * a; }
        float inv = 1.0f / fmaxf(sqrtf(ss), 1e-12f);
        #pragma unroll 4
        for (int d2 = 0; d2 < DDIM; d2++)
            *(__nv_bfloat16*)(buf + p * 272 + d2 * 2) =
                __float2bfloat16(slab[d2 * 256 + p] * inv);
        __syncthreads();
        #pragma unroll
        for (int it = 0; it < 16; it++) {
            int flat = it * 256 + p;
            int row = flat >> 4, c = flat & 15;
            *(uint4*)(g_patchB + ((size_t)b * NPX + half * PP + row) * DDIM + c * 8) =
                *(uint4*)(buf + row * 272 + c * 16);
        }
        __syncthreads();
    }
}

// Unified persistent GEMM: instance + patch tiles, A-stationary, cp.async
// double-buffered B, f16x2 exp epilogue.
__global__ void __launch_bounds__(128, 2) k_gemm() {
    extern __shared__ char smem[];
    uint32_t sa = smem_u32(smem);
    uint32_t sb0 = sa + 32768, sb1 = sa + 65536;
    int t = threadIdx.x, w = t >> 5, lane = t & 31;
    int g = lane >> 2, q = lane & 3;
    int wm = w >> 1, wn = w & 1;
    int u0 = blockIdx.x * CHUNK;
    int u1 = min(u0 + CHUNK, TOT_ALL);
    int nt = u1 - u0;
    if (nt <= 0) return;

    TileInfo t0 = dec_tile(u0);
    cpa_rows(sa, t0.a, t);
    cpa_rows(sb0, t0.b, t);
    CP_COMMIT();
    if (nt > 1) { TileInfo t1 = dec_tile(u0 + 1); cpa_rows(sb1, t1.b, t); }
    CP_COMMIT();
    CP_WAIT1();
    __syncthreads();

    const __nv_bfloat16* cura = t0.a;
    float* currow = t0.rowdst;
    float racc[4][2] = {{0.f,0.f},{0.f,0.f},{0.f,0.f},{0.f,0.f}};

    for (int s = 0; s < nt; s++) {
        TileInfo ti = dec_tile(u0 + s);
        uint32_t sbX = (s & 1) ? sb1 : sb0;
        float d[4][8][4];
        gemm128(d, sa, sbX, wm, wn, lane);

        uint32_t hacc01[4] = {0,0,0,0}, hacc23[4] = {0,0,0,0};
        uint32_t cacc[8] = {0,0,0,0,0,0,0,0};
        bool diag = ti.diag, post = ti.postile;
        #pragma unroll
        for (int mt = 0; mt < 4; mt++) {
            int rl = wm * 64 + mt * 16 + g;
            #pragma unroll
            for (int n2 = 0; n2 < 8; n2++) {
                int cl = wn * 64 + n2 * 8 + q * 2;
                float d0 = d[mt][n2][0], d1 = d[mt][n2][1];
                float d2 = d[mt][n2][2], d3 = d[mt][n2][3];
                if (post) {   // j = i ^ 256 positives (write both orientations)
                    if (rl == cl)         { ti.posrow[rl]     = d0; ti.poscol[cl]     = d0; }
                    if (rl == cl + 1)     { ti.posrow[rl]     = d1; ti.poscol[cl + 1] = d1; }
                    if (rl + 8 == cl)     { ti.posrow[rl + 8] = d2; ti.poscol[cl]     = d2; }
                    if (rl + 8 == cl + 1) { ti.posrow[rl + 8] = d3; ti.poscol[cl + 1] = d3; }
                }
                float a0 = fmaf(d0, SC, SHIFT), a1 = fmaf(d1, SC, SHIFT);
                float a2 = fmaf(d2, SC, SHIFT), a3 = fmaf(d3, SC, SHIFT);
                if (diag) {   // mask self-similarity
                    if (rl == cl)         a0 = -100.f;
                    if (rl == cl + 1)     a1 = -100.f;
                    if (rl + 8 == cl)     a2 = -100.f;
                    if (rl + 8 == cl + 1) a3 = -100.f;
                }
                uint32_t h01 = exp2pack(a0, a1);
                uint32_t h23 = exp2pack(a2, a3);
                hacc01[mt] = hadd2v(hacc01[mt], h01);
                hacc23[mt] = hadd2v(hacc23[mt], h23);
                cacc[n2]   = hadd2v(cacc[n2], hadd2v(h01, h23));
            }
        }
        #pragma unroll
        for (int mt = 0; mt < 4; mt++) {
            float2 r0 = unpackh(hacc01[mt]); racc[mt][0] += r0.x + r0.y;
            float2 r1 = unpackh(hacc23[mt]); racc[mt][1] += r1.x + r1.y;
        }
        if (!diag) {
            #pragma unroll
            for (int n2 = 0; n2 < 8; n2++) {
                float2 c = unpackh(cacc[n2]);
                float c0 = c.x, c1 = c.y;
                #pragma unroll
                for (int o = 4; o <= 16; o <<= 1) {
                    c0 += __shfl_xor_sync(0xffffffffu, c0, o);
                    c1 += __shfl_xor_sync(0xffffffffu, c1, o);
                }
                if (g == 0) {
                    atomicAdd(&ti.coldst[wn * 64 + n2 * 8 + q * 2], c0);
                    atomicAdd(&ti.coldst[wn * 64 + n2 * 8 + q * 2 + 1], c1);
                }
            }
        }
        __syncthreads();

        if (s + 1 == nt) break;
        TileInfo tn = dec_tile(u0 + s + 1);
        bool rel = (tn.a != cura);
        if (rel) {
            flush_rows(racc, currow, wm, lane);
            cura = tn.a; currow = tn.rowdst;
            cpa_rows(sa, tn.a, t);
        }
        if (s + 2 < nt) {
            TileInfo tp = dec_tile(u0 + s + 2);
            cpa_rows(sbX, tp.b, t);
        }
        CP_COMMIT();
        if (rel) { CP_WAIT0(); } else { CP_WAIT1(); }
        __syncthreads();
    }
    flush_rows(racc, currow, wm, lane);
}

// fused per-row loss reduce (instance: blocks [0,64), patch: [64,576))
__global__ void k_reduce() {
    int bid = blockIdx.x, tx = threadIdx.x;
    float part = 0.f;
    bool ins = (bid < N_INS / 256);
    if (ins) {
        int i = bid * 256 + tx;
        int ip = i ^ B_INS;
        float pos = 0.f;
        #pragma unroll 4
        for (int k = 0; k < DDIM; k++)
            pos = fmaf(g_embsT[(size_t)k * N_INS + i], g_embsT[(size_t)k * N_INS + ip], pos);
        part = __logf(g_row_sum[i]) + CADJ - pos * TEMP_INV;
    } else {
        int i = (bid - N_INS / 256) * 256 + tx;
        if (g_valid[i])
            part = __logf(g_prow[i]) + CADJ - g_ppos[i] * TEMP_INV;
    }
    __shared__ float red[256];
    red[tx] = part;
    __syncthreads();
    for (int o = 128; o; o >>= 1) {
        if (tx < o) red[tx] += red[tx + o];
        __syncthreads();
    }
    if (tx == 0) atomicAdd(ins ? &g_loss_ins : &g_loss_patch, (double)red[0]);
}

__global__ void k_final(float* out) {
    out[0] = (float)(g_loss_ins / (double)N_INS + g_loss_patch / (double)g_nvalid);
}

// ------------------------------------------------------------------
extern "C" void kernel_launch(void* const* d_in, const int* in_sizes, int n_in,
                              void* d_out, int out_size) {
    const float* v1i = (const float*)d_in[0];
    const float* v2i = (const float*)d_in[1];
    const float* v1p = (const float*)d_in[2];
    const float* v2p = (const float*)d_in[3];
    const int*   c1  = (const int*)d_in[4];
    const int*   c2  = (const int*)d_in[5];
    float* out = (float*)d_out;

    cudaFuncSetAttribute(k_norm_patch, cudaFuncAttributeMaxDynamicSharedMemorySize, SMEM_NORMP);
    cudaFuncSetAttribute(k_gemm,       cudaFuncAttributeMaxDynamicSharedMemorySize, SMEM_GEMM);

    k_norm_ins<<<N_INS / 8, 256>>>(v1i, v2i);
    k_norm_patch<<<BP, 256, SMEM_NORMP>>>(v1p, v2p, c1, c2);
    k_gemm<<<GRID_G, 128, SMEM_GEMM>>>();
    k_reduce<<<N_INS / 256 + (BP * NPX) / 256, 256>>>();
    k_final<<<1, 1>>>(out);
}

// round 15
// speedup vs baseline: 10.2330x; 1.2125x over previous
#include <cuda_runtime.h>
#include <cuda_bf16.h>
#include <math.h>
#include <stdint.h>

#define B_INS   8192
#define N_INS   16384
#define DDIM    128
#define BP      256
#define PP      256
#define NPX     512
#define TEMP_INV 10.0f
#define SC      14.426950408889634f   // 10 * log2(e)
#define SHIFT   (-4.426950408889634f) // 10 - SC  (args biased +10 to stay f16-normal)
#define CADJ    3.0685281944f         // 10 - 10*ln2 (undo the +10 exponent bias)
#define NT_INS  128
#define TOT_I   (NT_INS * (NT_INS + 1) / 2)   // 8256
#define TOT_P   (BP * 10)                      // 2560
#define TOT_ALL (TOT_I + TOT_P)                // 10816
#define CHUNK   37
#define GRID_G  293                            // ceil(10816/37), one wave @2 CTA/SM
#define SMEM_GEMM (3 * 32768)

// ---- scratch (device globals; no allocation allowed) ----
__device__ __align__(16) __nv_bfloat16 g_embsB[(size_t)N_INS * DDIM];
__device__ __align__(16) __nv_bfloat16 g_patchB[(size_t)BP * NPX * DDIM];
__device__ int    g_valid[BP * NPX];
__device__ float  g_row_sum[N_INS];
__device__ float  g_prow[BP * NPX];
__device__ float  g_ppos[BP * NPX];
__device__ double g_loss_ins;
__device__ double g_loss_patch;
__device__ int    g_nvalid;

// ------------------------- helpers -------------------------
__device__ __forceinline__ uint32_t smem_u32(const void* p) {
    uint32_t a;
    asm("{ .reg .u64 t; cvta.to.shared.u64 t, %1; cvt.u32.u64 %0, t; }" : "=r"(a) : "l"(p));
    return a;
}
__device__ __forceinline__ void ldsm4(uint32_t* r, uint32_t addr) {
    asm volatile("ldmatrix.sync.aligned.m8n8.x4.shared.b16 {%0,%1,%2,%3}, [%4];"
        : "=r"(r[0]), "=r"(r[1]), "=r"(r[2]), "=r"(r[3]) : "r"(addr));
}
__device__ __forceinline__ void mma16816(float* d, const uint32_t* a, const uint32_t* b) {
    asm volatile(
        "mma.sync.aligned.m16n8k16.row.col.f32.bf16.bf16.f32 "
        "{%0,%1,%2,%3}, {%4,%5,%6,%7}, {%8,%9}, {%0,%1,%2,%3};"
        : "+f"(d[0]), "+f"(d[1]), "+f"(d[2]), "+f"(d[3])
        : "r"(a[0]), "r"(a[1]), "r"(a[2]), "r"(a[3]), "r"(b[0]), "r"(b[1]));
}
__device__ __forceinline__ uint32_t exp2pack(float a0, float a1) {
    uint32_t h;
    asm("{ .reg .b32 t; cvt.rn.f16x2.f32 t, %2, %1; ex2.approx.f16x2 %0, t; }"
        : "=r"(h) : "f"(a0), "f"(a1));
    return h;
}
__device__ __forceinline__ uint32_t hadd2v(uint32_t a, uint32_t b) {
    uint32_t r; asm("add.rn.f16x2 %0, %1, %2;" : "=r"(r) : "r"(a), "r"(b)); return r;
}
__device__ __forceinline__ float2 unpackh(uint32_t h) {
    float2 f;
    asm("{ .reg .b16 l, u; mov.b32 {l, u}, %2; cvt.f32.f16 %0, l; cvt.f32.f16 %1, u; }"
        : "=f"(f.x), "=f"(f.y) : "r"(h));
    return f;
}
#define CP_COMMIT() asm volatile("cp.async.commit_group;")
#define CP_WAIT0()  asm volatile("cp.async.wait_group 0;")
#define CP_WAIT1()  asm volatile("cp.async.wait_group 1;")

__device__ __forceinline__ void cpa_rows(uint32_t dst, const __nv_bfloat16* __restrict__ src, int t) {
    #pragma unroll
    for (int it = 0; it < 16; it++) {
        int flat = it * 128 + t;
        int row = flat >> 4, c = flat & 15;
        uint32_t d = dst + row * 256 + ((c ^ (row & 7)) << 4);
        const void* g = src + (size_t)row * DDIM + c * 8;
        asm volatile("cp.async.cg.shared.global [%0], [%1], 16;" :: "r"(d), "l"(g));
    }
}

// 128x128x128 HMMA body: 4 warps, 64x64 warp tiles, d[4][8][4].
__device__ __forceinline__ void gemm128(float d[4][8][4], uint32_t sa, uint32_t sb,
                                        int wm, int wn, int lane) {
    int idx = lane >> 3, r = lane & 7;
    #pragma unroll
    for (int mt = 0; mt < 4; mt++)
        #pragma unroll
        for (int nt = 0; nt < 8; nt++)
            #pragma unroll
            for (int e = 0; e < 4; e++) d[mt][nt][e] = 0.f;
    #pragma unroll
    for (int s = 0; s < 8; s++) {
        uint32_t aa[4][4], bb[4][4];
        #pragma unroll
        for (int mt = 0; mt < 4; mt++) {
            int row = wm * 64 + mt * 16 + (idx & 1) * 8 + r;
            int c = 2 * s + (idx >> 1);
            ldsm4(aa[mt], sa + row * 256 + ((c ^ (row & 7)) << 4));
        }
        #pragma unroll
        for (int p = 0; p < 4; p++) {
            int row = wn * 64 + p * 16 + (idx >> 1) * 8 + r;
            int c = 2 * s + (idx & 1);
            ldsm4(bb[p], sb + row * 256 + ((c ^ (row & 7)) << 4));
        }
        #pragma unroll
        for (int mt = 0; mt < 4; mt++)
            #pragma unroll
            for (int nt = 0; nt < 8; nt++)
                mma16816(d[mt][nt], aa[mt], &bb[nt >> 1][(nt & 1) * 2]);
    }
}

__device__ __forceinline__ void flush_rows(float racc[4][2], float* dst, int wm, int lane) {
    int g = lane >> 2, q = lane & 3;
    #pragma unroll
    for (int mt = 0; mt < 4; mt++) {
        float r0 = racc[mt][0], r1 = racc[mt][1];
        r0 += __shfl_xor_sync(0xffffffffu, r0, 1);
        r0 += __shfl_xor_sync(0xffffffffu, r0, 2);
        r1 += __shfl_xor_sync(0xffffffffu, r1, 1);
        r1 += __shfl_xor_sync(0xffffffffu, r1, 2);
        if (q == 0) {
            atomicAdd(&dst[wm * 64 + mt * 16 + g], r0);
            atomicAdd(&dst[wm * 64 + mt * 16 + g + 8], r1);
        }
        racc[mt][0] = 0.f; racc[mt][1] = 0.f;
    }
}

// specialized tile epilogue: MODE 0 = clean, 1 = diag mask, 2 = positive capture
template<int MODE>
__device__ __forceinline__ void epi_tile(const float d[4][8][4], float racc[4][2],
                                         uint32_t cacc[8], int wm, int wn, int g, int q,
                                         float* posrow, float* poscol) {
    uint32_t hacc01[4] = {0,0,0,0}, hacc23[4] = {0,0,0,0};
    #pragma unroll
    for (int mt = 0; mt < 4; mt++) {
        int rl = wm * 64 + mt * 16 + g;
        #pragma unroll
        for (int n2 = 0; n2 < 8; n2++) {
            float a0 = fmaf(d[mt][n2][0], SC, SHIFT), a1 = fmaf(d[mt][n2][1], SC, SHIFT);
            float a2 = fmaf(d[mt][n2][2], SC, SHIFT), a3 = fmaf(d[mt][n2][3], SC, SHIFT);
            if (MODE == 1) {
                int cl = wn * 64 + n2 * 8 + q * 2;
                if (rl == cl)         a0 = -100.f;
                if (rl == cl + 1)     a1 = -100.f;
                if (rl + 8 == cl)     a2 = -100.f;
                if (rl + 8 == cl + 1) a3 = -100.f;
            }
            if (MODE == 2) {
                int cl = wn * 64 + n2 * 8 + q * 2;
                if (rl == cl)         { posrow[rl]     = d[mt][n2][0]; poscol[cl]     = d[mt][n2][0]; }
                if (rl == cl + 1)     { posrow[rl]     = d[mt][n2][1]; poscol[cl + 1] = d[mt][n2][1]; }
                if (rl + 8 == cl)     { posrow[rl + 8] = d[mt][n2][2]; poscol[cl]     = d[mt][n2][2]; }
                if (rl + 8 == cl + 1) { posrow[rl + 8] = d[mt][n2][3]; poscol[cl + 1] = d[mt][n2][3]; }
            }
            uint32_t h01 = exp2pack(a0, a1);
            uint32_t h23 = exp2pack(a2, a3);
            hacc01[mt] = hadd2v(hacc01[mt], h01);
            hacc23[mt] = hadd2v(hacc23[mt], h23);
            cacc[n2]   = hadd2v(cacc[n2], hadd2v(h01, h23));
        }
    }
    #pragma unroll
    for (int mt = 0; mt < 4; mt++) {
        float2 r0 = unpackh(hacc01[mt]); racc[mt][0] += r0.x + r0.y;
        float2 r1 = unpackh(hacc23[mt]); racc[mt][1] += r1.x + r1.y;
    }
}

// tile decode
__device__ __forceinline__ void dec_ins(int u, int& bi, int& bj) {
    int p = u / 129, t = u - p * 129;
    int lenA = 128 - p;
    if (t < lenA) { bi = p; bj = p + t; }
    else { bi = 127 - p; bj = (127 - p) + (t - lenA); }
}
__device__ __forceinline__ void dec_patch(int u, int& b, int& ti, int& tj) {
    int qq = u / 5, t = u - qq * 5;
    b = qq >> 1;
    if ((qq & 1) == 0) { if (t < 4) { ti = 0; tj = t; } else { ti = 3; tj = 3; } }
    else               { if (t < 3) { ti = 1; tj = 1 + t; } else { ti = 2; tj = t - 1; } }
}

struct TileInfo {
    const __nv_bfloat16 *a, *b;
    float *rowdst, *coldst;
    float *posrow, *poscol;
    bool diag, postile;
};
__device__ __forceinline__ TileInfo dec_tile(int u) {
    TileInfo ti;
    if (u < TOT_I) {
        int bi, bj; dec_ins(u, bi, bj);
        ti.a = g_embsB + (size_t)bi * 128 * DDIM;
        ti.b = g_embsB + (size_t)bj * 128 * DDIM;
        ti.rowdst = &g_row_sum[bi * 128];
        ti.coldst = &g_row_sum[bj * 128];
        ti.diag = (bi == bj); ti.postile = false;
        ti.posrow = 0; ti.poscol = 0;
    } else {
        int b, t_i, t_j; dec_patch(u - TOT_I, b, t_i, t_j);
        ti.a = g_patchB + ((size_t)b * NPX + t_i * 128) * DDIM;
        ti.b = g_patchB + ((size_t)b * NPX + t_j * 128) * DDIM;
        ti.rowdst = &g_prow[b * NPX + t_i * 128];
        ti.coldst = &g_prow[b * NPX + t_j * 128];
        ti.diag = (t_i == t_j);
        ti.postile = (t_j == (t_i ^ 2));
        ti.posrow = &g_ppos[b * NPX + t_i * 128];
        ti.poscol = &g_ppos[b * NPX + t_j * 128];
    }
    return ti;
}

// ------------------------- kernels -------------------------
// instance norm + global zero-init (fused)
__global__ void k_norm_ins(const float* __restrict__ v1, const float* __restrict__ v2) {
    int gt = blockIdx.x * blockDim.x + threadIdx.x;
    if (gt < N_INS) g_row_sum[gt] = 0.0f;
    if (gt < BP * NPX) g_prow[gt] = 0.0f;
    if (gt == 0) { g_loss_ins = 0.0; g_loss_patch = 0.0; g_nvalid = 0; }

    int warp = gt >> 5;
    int lane = threadIdx.x & 31;
    if (warp >= N_INS) return;
    const float* src = (warp < B_INS) ? (v1 + (size_t)warp * DDIM)
                                      : (v2 + (size_t)(warp - B_INS) * DDIM);
    float4 v = ((const float4*)src)[lane];
    float ss = v.x*v.x + v.y*v.y + v.z*v.z + v.w*v.w;
    #pragma unroll
    for (int o = 16; o; o >>= 1) ss += __shfl_xor_sync(0xffffffffu, ss, o);
    float inv = 1.0f / fmaxf(sqrtf(ss), 1e-12f);
    __nv_bfloat162* dst = (__nv_bfloat162*)(g_embsB + (size_t)warp * DDIM + lane * 4);
    dst[0] = __floats2bfloat162_rn(v.x * inv, v.y * inv);
    dst[1] = __floats2bfloat162_rn(v.z * inv, v.w * inv);
}

// patch norm: single global pass via SMEM slab
#define SMEM_NORMP (131072 + 69632)   // slab[128][256] f32 + buf 256x272
__global__ void k_norm_patch(const float* __restrict__ v1, const float* __restrict__ v2,
                             const int* __restrict__ c1, const int* __restrict__ c2) {
    extern __shared__ char psm[];
    float* slab = (float*)psm;
    char*  buf  = psm + 131072;
    int b = blockIdx.x, p = threadIdx.x;

    int f1 = (c1[b * PP + p] != 0), f2 = (c2[b * PP + p] != 0);
    g_valid[b * NPX + p]      = f1;
    g_valid[b * NPX + PP + p] = f2;
    int cnt = __popc(__ballot_sync(0xffffffffu, f1)) + __popc(__ballot_sync(0xffffffffu, f2));
    if ((p & 31) == 0) atomicAdd(&g_nvalid, cnt);

    #pragma unroll
    for (int half = 0; half < 2; half++) {
        const float4* src = (const float4*)((half ? v2 : v1) + (size_t)b * DDIM * PP);
        float4* sl4 = (float4*)slab;
        #pragma unroll
        for (int it = 0; it < 32; it++)
            sl4[it * 256 + p] = src[it * 256 + p];
        __syncthreads();
        float ss = 0.f;
        #pragma unroll 4
        for (int d2 = 0; d2 < DDIM; d2++) { float a = slab[d2 * 256 + p]; ss += a * a; }
        float inv = 1.0f / fmaxf(sqrtf(ss), 1e-12f);
        #pragma unroll 4
        for (int d2 = 0; d2 < DDIM; d2++)
            *(__nv_bfloat16*)(buf + p * 272 + d2 * 2) =
                __float2bfloat16(slab[d2 * 256 + p] * inv);
        __syncthreads();
        #pragma unroll
        for (int it = 0; it < 16; it++) {
            int flat = it * 256 + p;
            int row = flat >> 4, c = flat & 15;
            *(uint4*)(g_patchB + ((size_t)b * NPX + half * PP + row) * DDIM + c * 8) =
                *(uint4*)(buf + row * 272 + c * 16);
        }
        __syncthreads();
    }
}

// Unified persistent GEMM
__global__ void __launch_bounds__(128, 2) k_gemm() {
    extern __shared__ char smem[];
    uint32_t sa = smem_u32(smem);
    uint32_t sb0 = sa + 32768, sb1 = sa + 65536;
    int t = threadIdx.x, w = t >> 5, lane = t & 31;
    int g = lane >> 2, q = lane & 3;
    int wm = w >> 1, wn = w & 1;
    int u0 = blockIdx.x * CHUNK;
    int u1 = min(u0 + CHUNK, TOT_ALL);
    int nt = u1 - u0;
    if (nt <= 0) return;

    TileInfo t0 = dec_tile(u0);
    cpa_rows(sa, t0.a, t);
    cpa_rows(sb0, t0.b, t);
    CP_COMMIT();
    if (nt > 1) { TileInfo t1 = dec_tile(u0 + 1); cpa_rows(sb1, t1.b, t); }
    CP_COMMIT();
    CP_WAIT1();
    __syncthreads();

    const __nv_bfloat16* cura = t0.a;
    float* currow = t0.rowdst;
    float racc[4][2] = {{0.f,0.f},{0.f,0.f},{0.f,0.f},{0.f,0.f}};

    for (int s = 0; s < nt; s++) {
        TileInfo ti = dec_tile(u0 + s);
        uint32_t sbX = (s & 1) ? sb1 : sb0;
        float d[4][8][4];
        gemm128(d, sa, sbX, wm, wn, lane);

        uint32_t cacc[8] = {0,0,0,0,0,0,0,0};
        if (ti.diag)         epi_tile<1>(d, racc, cacc, wm, wn, g, q, 0, 0);
        else if (ti.postile) epi_tile<2>(d, racc, cacc, wm, wn, g, q, ti.posrow, ti.poscol);
        else                 epi_tile<0>(d, racc, cacc, wm, wn, g, q, 0, 0);

        if (!ti.diag) {
            #pragma unroll
            for (int n2 = 0; n2 < 8; n2++) {
                float2 c = unpackh(cacc[n2]);
                float c0 = c.x, c1 = c.y;
                #pragma unroll
                for (int o = 4; o <= 16; o <<= 1) {
                    c0 += __shfl_xor_sync(0xffffffffu, c0, o);
                    c1 += __shfl_xor_sync(0xffffffffu, c1, o);
                }
                if (g == 0) {
                    atomicAdd(&ti.coldst[wn * 64 + n2 * 8 + q * 2], c0);
                    atomicAdd(&ti.coldst[wn * 64 + n2 * 8 + q * 2 + 1], c1);
                }
            }
        }
        __syncthreads();

        if (s + 1 == nt) break;
        TileInfo tn = dec_tile(u0 + s + 1);
        bool rel = (tn.a != cura);
        if (rel) {
            flush_rows(racc, currow, wm, lane);
            cura = tn.a; currow = tn.rowdst;
            cpa_rows(sa, tn.a, t);
        }
        if (s + 2 < nt) {
            TileInfo tp = dec_tile(u0 + s + 2);
            cpa_rows(sbX, tp.b, t);
        }
        CP_COMMIT();
        if (rel) { CP_WAIT0(); } else { CP_WAIT1(); }
        __syncthreads();
    }
    flush_rows(racc, currow, wm, lane);
}

// fused loss reduce. Blocks [0,2048): instance (8 rows/block, warp-per-row
// coalesced bf16 pos dot). Blocks [2048,2560): patch rows.
__global__ void k_reduce() {
    int bid = blockIdx.x, tx = threadIdx.x;
    if (bid < N_INS / 8) {
        int w = tx >> 5, lane = tx & 31;
        int i = bid * 8 + w;
        uint2 ua = ((const uint2*)(g_embsB + (size_t)i * DDIM))[lane];
        uint2 ub = ((const uint2*)(g_embsB + (size_t)(i ^ B_INS) * DDIM))[lane];
        float2 a0 = __bfloat1622float2(*(__nv_bfloat162*)&ua.x);
        float2 a1 = __bfloat1622float2(*(__nv_bfloat162*)&ua.y);
        float2 b0 = __bfloat1622float2(*(__nv_bfloat162*)&ub.x);
        float2 b1 = __bfloat1622float2(*(__nv_bfloat162*)&ub.y);
        float pos = a0.x*b0.x + a0.y*b0.y + a1.x*b1.x + a1.y*b1.y;
        #pragma unroll
        for (int o = 16; o; o >>= 1) pos += __shfl_xor_sync(0xffffffffu, pos, o);
        __shared__ float wl[8];
        if (lane == 0)
            wl[w] = __logf(g_row_sum[i]) + CADJ - pos * TEMP_INV;
        __syncthreads();
        if (tx == 0) {
            float s = 0.f;
            #pragma unroll
            for (int k = 0; k < 8; k++) s += wl[k];
            atomicAdd(&g_loss_ins, (double)s);
        }
    } else {
        int i = (bid - N_INS / 8) * 256 + tx;
        float part = 0.f;
        if (g_valid[i])
            part = __logf(g_prow[i]) + CADJ - g_ppos[i] * TEMP_INV;
        __shared__ float red[256];
        red[tx] = part;
        __syncthreads();
        for (int o = 128; o; o >>= 1) {
            if (tx < o) red[tx] += red[tx + o];
            __syncthreads();
        }
        if (tx == 0) atomicAdd(&g_loss_patch, (double)red[0]);
    }
}

__global__ void k_final(float* out) {
    out[0] = (float)(g_loss_ins / (double)N_INS + g_loss_patch / (double)g_nvalid);
}

// ------------------------------------------------------------------
extern "C" void kernel_launch(void* const* d_in, const int* in_sizes, int n_in,
                              void* d_out, int out_size) {
    const float* v1i = (const float*)d_in[0];
    const float* v2i = (const float*)d_in[1];
    const float* v1p = (const float*)d_in[2];
    const float* v2p = (const float*)d_in[3];
    const int*   c1  = (const int*)d_in[4];
    const int*   c2  = (const int*)d_in[5];
    float* out = (float*)d_out;

    cudaFuncSetAttribute(k_norm_patch, cudaFuncAttributeMaxDynamicSharedMemorySize, SMEM_NORMP);
    cudaFuncSetAttribute(k_gemm,       cudaFuncAttributeMaxDynamicSharedMemorySize, SMEM_GEMM);

    k_norm_ins<<<N_INS / 8, 256>>>(v1i, v2i);
    k_norm_patch<<<BP, 256, SMEM_NORMP>>>(v1p, v2p, c1, c2);
    k_gemm<<<GRID_G, 128, SMEM_GEMM>>>();
    k_reduce<<<N_INS / 8 + (BP * NPX) / 256, 256>>>();
    k_final<<<1, 1>>>(out);
}